// round 5
// baseline (speedup 1.0000x reference)
#include <cuda_runtime.h>
#include <math.h>

// Problem constants
#define BB 16
#define NN 2048
#define SS 512      // npoint
#define KK 32       // nsample
#define PP (BB*SS*KK)   // 262144 total "points" through the MLP
#define BSS (BB*SS)
#define C0 67
#define C0P 68      // padded input channels
#define O1 64
#define O2 64
#define O3 128

typedef unsigned long long ull_t;

#define FMA2(d, a, b, c) \
    asm("fma.rn.f32x2 %0, %1, %2, %3;" : "=l"(d) : "l"(a), "l"(b), "l"(c))

__device__ __forceinline__ float ull_lo(ull_t v) {
    return __uint_as_float((unsigned)(v & 0xffffffffull));
}
__device__ __forceinline__ float ull_hi(ull_t v) {
    return __uint_as_float((unsigned)(v >> 32));
}
__device__ __forceinline__ ull_t dup2(float v) {
    unsigned u = __float_as_uint(v);
    ull_t r;
    asm("mov.b64 %0, {%1, %1};" : "=l"(r) : "r"(u));
    return r;
}

// ---------------- scratch ----------------
static __device__ __align__(16) float g_featT[BB*NN*C0P];         // 8.9 MB  [b][n][c]
static __device__ int   g_bidx[PP];                               // ball-query indices
static __device__ __align__(16) float g_bufA[(size_t)O1*PP];      // 67 MB   (conv1 out)
static __device__ __align__(16) float g_bufB[(size_t)O2*PP];      // 67 MB   (conv2 out)
static __device__ __align__(16) float g_max3[(size_t)O3*BSS];     // 4 MB
static __device__ __align__(16) float g_min3[(size_t)O3*BSS];     // 4 MB
static __device__ float g_stat1[2*O1], g_stat2[2*O2], g_stat3[2*O3];
static __device__ float g_sc1[O1], g_sh1[O1];
static __device__ float g_sc2[O2], g_sh2[O2];
static __device__ float g_sc3[O3], g_sh3[O3];

// ---------------- fused: blocks 0..15 = FPS (one per batch), 16..143 = build featT ----------------
__global__ __launch_bounds__(256)
void build_fps_kernel(const float* __restrict__ xyz,
                      const float* __restrict__ pts,
                      float* __restrict__ out) {
    __shared__ float sx[NN], sy[NN], sz[NN];
    __shared__ ull_t swk[2][8];
    int tid = threadIdx.x;

    if (blockIdx.x >= 16) {
        // ---------------- build featT ----------------
        if (blockIdx.x == 16) {
            if (tid < 2*O1) g_stat1[tid] = 0.f;
            if (tid < 2*O2) g_stat2[tid] = 0.f;
            if (tid < 2*O3) g_stat3[tid] = 0.f;
        }
        int id = (blockIdx.x - 16) * 256 + tid;   // (b,n) flat, 32768 total
        int b = id >> 11, n = id & 2047;
        const float* xb = xyz + b * 3 * NN;
        const float* pb2 = pts + (size_t)b * 64 * NN;
        float* dst = g_featT + (size_t)id * C0P;
        float4 v;
        v.x = xb[n]; v.y = xb[NN + n]; v.z = xb[2*NN + n]; v.w = pb2[n];
        ((float4*)dst)[0] = v;
#pragma unroll
        for (int g = 1; g < 17; ++g) {
            int ch = 4*g - 3;
            v.x = pb2[(ch+0)*NN + n];
            v.y = pb2[(ch+1)*NN + n];
            v.z = pb2[(ch+2)*NN + n];
            v.w = (4*g + 3 < C0) ? pb2[(ch+3)*NN + n] : 0.f;
            ((float4*)dst)[g] = v;
        }
        return;
    }

    // ---------------- FPS ----------------
    int b = blockIdx.x;
    const float* xb = xyz + b * 3 * NN;
    int lane = tid & 31, wid = tid >> 5;
    for (int i = tid; i < NN; i += 256) {
        sx[i] = xb[i]; sy[i] = xb[NN + i]; sz[i] = xb[2*NN + i];
    }
    __syncthreads();
    float px[8], py[8], pz[8], dist[8];
#pragma unroll
    for (int i = 0; i < 8; ++i) {
        int n = tid + i*256;
        px[i] = sx[n]; py[i] = sy[n]; pz[i] = sz[n];
        dist[i] = 1e10f;
    }
    int far = 0, pb = 0;
    float* ob = out + b * 3 * SS;
    for (int it = 0; it < SS; ++it) {
        float cx = sx[far], cy = sy[far], cz = sz[far];
        if (tid == 0) { ob[it] = cx; ob[SS+it] = cy; ob[2*SS+it] = cz; }
        unsigned bb = 0u; unsigned bi = 0xffffffffu;
#pragma unroll
        for (int i = 0; i < 8; ++i) {
            float dx = px[i]-cx, dy = py[i]-cy, dz = pz[i]-cz;
            float d = dx*dx; d += dy*dy; d += dz*dz;
            float dd = fminf(dist[i], d); dist[i] = dd;
            unsigned bits = __float_as_uint(dd);   // monotone for dd >= 0
            if (bits > bb) { bb = bits; bi = (unsigned)(tid + i*256); }
        }
        unsigned wm = __reduce_max_sync(0xffffffffu, bb);
        unsigned cand = (bb == wm) ? bi : 0xffffffffu;
        unsigned wi = __reduce_min_sync(0xffffffffu, cand);   // first-index tie-break
        if (lane == 0) swk[pb][wid] = ((ull_t)wm << 32) | (unsigned)(~wi);
        __syncthreads();
        // every thread scalar-maxes the 8 staged packed keys (broadcast LDS.64)
        ull_t k = swk[pb][0];
#pragma unroll
        for (int i2 = 1; i2 < 8; ++i2) {
            ull_t k2 = swk[pb][i2];
            if (k2 > k) k = k2;
        }
        far = (int)(~(unsigned)k);
        pb ^= 1;
    }
}

// ---------------- ball query: smem-staged xyz; warp per center ----------------
__global__ __launch_bounds__(256)
void ball_kernel(const float* __restrict__ xyz,
                 const float* __restrict__ newxyz /* = d_out head */) {
    __shared__ float sx[NN], sy[NN], sz[NN];
    int b = blockIdx.x >> 6, schunk = blockIdx.x & 63;
    const float* xb = xyz + b * 3 * NN;
    for (int i = threadIdx.x; i < NN; i += 256) {
        sx[i] = xb[i]; sy[i] = xb[NN + i]; sz[i] = xb[2*NN + i];
    }
    __syncthreads();
    int w = threadIdx.x >> 5, lane = threadIdx.x & 31;
    int s = schunk * 8 + w;
    float cx = newxyz[b*3*SS + s];
    float cy = newxyz[b*3*SS + SS + s];
    float cz = newxyz[b*3*SS + 2*SS + s];
    int* dst = g_bidx + (b*SS + s) * KK;
    const float R2 = 0.04f;
    int count = 0, first = -1;
    for (int r = 0; r < NN/32; ++r) {
        int n = r*32 + lane;
        float dx = cx - sx[n], dy = cy - sy[n], dz = cz - sz[n];
        float d = dx*dx; d += dy*dy; d += dz*dz;
        bool q = (d <= R2);
        unsigned m = __ballot_sync(0xffffffffu, q);
        if (first < 0 && m) first = r*32 + __ffs(m) - 1;
        int pos = count + __popc(m & ((1u << lane) - 1u));
        if (q && pos < KK) dst[pos] = n;
        count += __popc(m);
        if (count >= KK) break;
    }
    if (count < KK && lane >= count && lane < KK) dst[lane] = first;
}

// ---------------- conv1: gather + GEMM(67->64) f32x2 (reg-dup W) + bias + BN stats ----------------
__global__ __launch_bounds__(256, 4)
void conv1_kernel(const float* __restrict__ w0, const float* __restrict__ b0,
                  const float* __restrict__ newxyz) {
    extern __shared__ float sm[];
    float* Ws = sm;                 // [68][64] compact
    float* Xs = sm + C0P * O1;      // [68][128]
    int tid = threadIdx.x, lane = tid & 31, w = tid >> 5;
    int pbase = blockIdx.x * 128;

    // W load (compact, pad rows zeroed)
    {
        int o = tid & 63, cq = tid >> 6;
#pragma unroll
        for (int k = 0; k < 17; ++k) {
            int c = cq*17 + k;
            Ws[c*64 + o] = (c < C0) ? w0[o*C0 + c] : 0.f;
        }
    }
    // X gather
    {
        int pg = w & 3, half = w >> 2;
        int p = pg*32 + lane;
        int gp = pbase + p;
        int n = g_bidx[gp];
        int sg = gp >> 5;
        int bbt = sg >> 9, ss = sg & 511;
        const float* row = g_featT + ((size_t)(bbt*NN + n)) * C0P;
        float ccx = 0.f, ccy = 0.f, ccz = 0.f;
        if (half == 0) {
            ccx = newxyz[bbt*3*SS + ss];
            ccy = newxyz[bbt*3*SS + SS + ss];
            ccz = newxyz[bbt*3*SS + 2*SS + ss];
        }
        int ga = half ? 9 : 0, gb = half ? 17 : 9;
        for (int g = ga; g < gb; ++g) {
            float4 v = ((const float4*)row)[g];
            if (g == 0) { v.x -= ccx; v.y -= ccy; v.z -= ccz; }
            Xs[(4*g+0)*128 + p] = v.x;
            Xs[(4*g+1)*128 + p] = v.y;
            Xs[(4*g+2)*128 + p] = v.z;
            Xs[(4*g+3)*128 + p] = v.w;
        }
    }
    __syncthreads();

    int og = tid & 15, o = og*4;
    int pgg = tid >> 4, pp = pgg*8;
    ull_t accp[4][4];
#pragma unroll
    for (int i = 0; i < 4; ++i)
#pragma unroll
        for (int j = 0; j < 4; ++j) accp[i][j] = 0ull;

#pragma unroll 4
    for (int c = 0; c < C0P; ++c) {
        ulonglong2 xa = *(const ulonglong2*)(Xs + c*128 + pp);
        ulonglong2 xb2 = *(const ulonglong2*)(Xs + c*128 + pp + 4);
        float4 wv = *(const float4*)(Ws + c*64 + o);
        ull_t xs[4] = {xa.x, xa.y, xb2.x, xb2.y};
        ull_t ws[4] = {dup2(wv.x), dup2(wv.y), dup2(wv.z), dup2(wv.w)};
#pragma unroll
        for (int i = 0; i < 4; ++i)
#pragma unroll
            for (int j = 0; j < 4; ++j)
                FMA2(accp[i][j], xs[i], ws[j], accp[i][j]);
    }
    // unpack (bit-exact vs scalar)
    float acc[8][4];
#pragma unroll
    for (int i = 0; i < 4; ++i)
#pragma unroll
        for (int j = 0; j < 4; ++j) {
            acc[2*i][j] = ull_lo(accp[i][j]);
            acc[2*i+1][j] = ull_hi(accp[i][j]);
        }
    float4 bias = *(const float4*)(b0 + o);
    float bv[4] = {bias.x, bias.y, bias.z, bias.w};
#pragma unroll
    for (int i = 0; i < 8; ++i)
#pragma unroll
        for (int j = 0; j < 4; ++j) acc[i][j] += bv[j];

#pragma unroll
    for (int j = 0; j < 4; ++j) {
        float* dst = g_bufA + (size_t)(o+j)*PP + pbase + pp;
        float4 u0 = {acc[0][j], acc[1][j], acc[2][j], acc[3][j]};
        float4 u1 = {acc[4][j], acc[5][j], acc[6][j], acc[7][j]};
        ((float4*)dst)[0] = u0; ((float4*)dst)[1] = u1;
    }
    float sj[4] = {0,0,0,0}, qj[4] = {0,0,0,0};
#pragma unroll
    for (int i = 0; i < 8; ++i)
#pragma unroll
        for (int j = 0; j < 4; ++j) { sj[j] += acc[i][j]; qj[j] += acc[i][j]*acc[i][j]; }
    __syncthreads();
    float* red = Xs;   // overlay: [2][16][64]
    {
        float4 a = {sj[0], sj[1], sj[2], sj[3]};
        float4 b2 = {qj[0], qj[1], qj[2], qj[3]};
        *(float4*)(red + pgg*64 + o) = a;
        *(float4*)(red + 1024 + pgg*64 + o) = b2;
    }
    __syncthreads();
    if (tid < 64) {
        float S = 0.f, Q = 0.f;
#pragma unroll
        for (int g = 0; g < 16; ++g) { S += red[g*64 + tid]; Q += red[1024 + g*64 + tid]; }
        atomicAdd(&g_stat1[tid], S);
        atomicAdd(&g_stat1[64 + tid], Q);
    }
}

// ---------------- BN finalize ----------------
__global__ void bnfin_kernel(int layer, const float* __restrict__ g,
                             const float* __restrict__ bt) {
    int o = threadIdx.x;
    const float* stat; float* sc; float* sh; int C;
    if (layer == 1)      { stat = g_stat1; sc = g_sc1; sh = g_sh1; C = O1; }
    else if (layer == 2) { stat = g_stat2; sc = g_sc2; sh = g_sh2; C = O2; }
    else                 { stat = g_stat3; sc = g_sc3; sh = g_sh3; C = O3; }
    if (o >= C) return;
    const float invN = 1.f / (float)PP;
    float mean = stat[o] * invN;
    float var = fmaxf(stat[C + o] * invN - mean*mean, 0.f);
    float is = rsqrtf(var + 1e-5f);
    float s = g[o] * is;
    sc[o] = s;
    sh[o] = fmaf(-mean, s, bt[o]);
}

// ---------------- conv2: BN1+ReLU on load, GEMM(64->64) f32x2 (reg-dup W) ----------------
__global__ __launch_bounds__(256, 4)
void conv2_kernel(const float* __restrict__ w1, const float* __restrict__ b1) {
    extern __shared__ float sm[];
    float* Ws = sm;                 // [64][64]
    float* Xs = sm + 64*64;         // [64][128]
    int tid = threadIdx.x, lane = tid & 31, w = tid >> 5;
    int pbase = blockIdx.x * 128;
    {
        int o = tid & 63, cq = tid >> 6;
#pragma unroll
        for (int k = 0; k < 16; ++k) {
            int c = cq*16 + k;
            Ws[c*64 + o] = w1[o*64 + c];
        }
    }
    for (int c = w; c < 64; c += 8) {
        float sc = g_sc1[c], sh = g_sh1[c];
        float4 v = *(const float4*)(g_bufA + (size_t)c*PP + pbase + lane*4);
        v.x = fmaxf(fmaf(v.x, sc, sh), 0.f);
        v.y = fmaxf(fmaf(v.y, sc, sh), 0.f);
        v.z = fmaxf(fmaf(v.z, sc, sh), 0.f);
        v.w = fmaxf(fmaf(v.w, sc, sh), 0.f);
        *(float4*)(Xs + c*128 + lane*4) = v;
    }
    __syncthreads();

    int og = tid & 15, o = og*4;
    int pgg = tid >> 4, pp = pgg*8;
    ull_t accp[4][4];
#pragma unroll
    for (int i = 0; i < 4; ++i)
#pragma unroll
        for (int j = 0; j < 4; ++j) accp[i][j] = 0ull;
#pragma unroll 4
    for (int c = 0; c < 64; ++c) {
        ulonglong2 xa = *(const ulonglong2*)(Xs + c*128 + pp);
        ulonglong2 xb2 = *(const ulonglong2*)(Xs + c*128 + pp + 4);
        float4 wv = *(const float4*)(Ws + c*64 + o);
        ull_t xs[4] = {xa.x, xa.y, xb2.x, xb2.y};
        ull_t ws[4] = {dup2(wv.x), dup2(wv.y), dup2(wv.z), dup2(wv.w)};
#pragma unroll
        for (int i = 0; i < 4; ++i)
#pragma unroll
            for (int j = 0; j < 4; ++j)
                FMA2(accp[i][j], xs[i], ws[j], accp[i][j]);
    }
    float acc[8][4];
#pragma unroll
    for (int i = 0; i < 4; ++i)
#pragma unroll
        for (int j = 0; j < 4; ++j) {
            acc[2*i][j] = ull_lo(accp[i][j]);
            acc[2*i+1][j] = ull_hi(accp[i][j]);
        }
    float4 bias = *(const float4*)(b1 + o);
    float bv[4] = {bias.x, bias.y, bias.z, bias.w};
#pragma unroll
    for (int i = 0; i < 8; ++i)
#pragma unroll
        for (int j = 0; j < 4; ++j) acc[i][j] += bv[j];
#pragma unroll
    for (int j = 0; j < 4; ++j) {
        float* dst = g_bufB + (size_t)(o+j)*PP + pbase + pp;
        float4 u0 = {acc[0][j], acc[1][j], acc[2][j], acc[3][j]};
        float4 u1 = {acc[4][j], acc[5][j], acc[6][j], acc[7][j]};
        ((float4*)dst)[0] = u0; ((float4*)dst)[1] = u1;
    }
    float sj[4] = {0,0,0,0}, qj[4] = {0,0,0,0};
#pragma unroll
    for (int i = 0; i < 8; ++i)
#pragma unroll
        for (int j = 0; j < 4; ++j) { sj[j] += acc[i][j]; qj[j] += acc[i][j]*acc[i][j]; }
    __syncthreads();
    float* red = Xs;
    {
        float4 a = {sj[0], sj[1], sj[2], sj[3]};
        float4 b2 = {qj[0], qj[1], qj[2], qj[3]};
        *(float4*)(red + pgg*64 + o) = a;
        *(float4*)(red + 1024 + pgg*64 + o) = b2;
    }
    __syncthreads();
    if (tid < 64) {
        float S = 0.f, Q = 0.f;
#pragma unroll
        for (int g = 0; g < 16; ++g) { S += red[g*64 + tid]; Q += red[1024 + g*64 + tid]; }
        atomicAdd(&g_stat2[tid], S);
        atomicAdd(&g_stat2[64 + tid], Q);
    }
}

// ---------------- conv3: BN2+ReLU on load, GEMM(64->128) f32x2 (reg-dup W), fused max/min ----------------
__global__ __launch_bounds__(256)
void conv3_kernel(const float* __restrict__ w2, const float* __restrict__ b2p) {
    extern __shared__ float sm[];
    float* Ws = sm;                 // [64][128]
    float* Xs = sm + 64*128;        // [64][128]
    int tid = threadIdx.x, lane = tid & 31, w = tid >> 5;
    int pbase = blockIdx.x * 128;
    {
        int o = tid & 127, ch = tid >> 7;
#pragma unroll
        for (int cc = 0; cc < 32; ++cc) {
            int c = ch*32 + cc;
            Ws[c*128 + o] = w2[o*64 + c];
        }
    }
    for (int c = w; c < 64; c += 8) {
        float sc = g_sc2[c], sh = g_sh2[c];
        float4 v = *(const float4*)(g_bufB + (size_t)c*PP + pbase + lane*4);
        v.x = fmaxf(fmaf(v.x, sc, sh), 0.f);
        v.y = fmaxf(fmaf(v.y, sc, sh), 0.f);
        v.z = fmaxf(fmaf(v.z, sc, sh), 0.f);
        v.w = fmaxf(fmaf(v.w, sc, sh), 0.f);
        *(float4*)(Xs + c*128 + lane*4) = v;
    }
    __syncthreads();

    int og = tid & 15, o = og*8;
    int pgg = tid >> 4, pp = pgg*8;
    ull_t accp[4][8];
#pragma unroll
    for (int i = 0; i < 4; ++i)
#pragma unroll
        for (int j = 0; j < 8; ++j) accp[i][j] = 0ull;
#pragma unroll 2
    for (int c = 0; c < 64; ++c) {
        ulonglong2 xa = *(const ulonglong2*)(Xs + c*128 + pp);
        ulonglong2 xb2 = *(const ulonglong2*)(Xs + c*128 + pp + 4);
        float4 wa = *(const float4*)(Ws + c*128 + o);
        float4 wb = *(const float4*)(Ws + c*128 + o + 4);
        ull_t xs[4] = {xa.x, xa.y, xb2.x, xb2.y};
        ull_t ws[8] = {dup2(wa.x), dup2(wa.y), dup2(wa.z), dup2(wa.w),
                       dup2(wb.x), dup2(wb.y), dup2(wb.z), dup2(wb.w)};
#pragma unroll
        for (int i = 0; i < 4; ++i)
#pragma unroll
            for (int j = 0; j < 8; ++j)
                FMA2(accp[i][j], xs[i], ws[j], accp[i][j]);
    }
    float acc[8][8];
#pragma unroll
    for (int i = 0; i < 4; ++i)
#pragma unroll
        for (int j = 0; j < 8; ++j) {
            acc[2*i][j] = ull_lo(accp[i][j]);
            acc[2*i+1][j] = ull_hi(accp[i][j]);
        }
    float4 ba = *(const float4*)(b2p + o);
    float4 bbv = *(const float4*)(b2p + o + 4);
    float bv[8] = {ba.x, ba.y, ba.z, ba.w, bbv.x, bbv.y, bbv.z, bbv.w};
#pragma unroll
    for (int i = 0; i < 8; ++i)
#pragma unroll
        for (int j = 0; j < 8; ++j) acc[i][j] += bv[j];

    float sj[8], qj[8], mxv[8], mnv[8];
#pragma unroll
    for (int j = 0; j < 8; ++j) {
        sj[j] = acc[0][j]; qj[j] = acc[0][j]*acc[0][j];
        mxv[j] = acc[0][j]; mnv[j] = acc[0][j];
    }
#pragma unroll
    for (int i = 1; i < 8; ++i)
#pragma unroll
        for (int j = 0; j < 8; ++j) {
            sj[j] += acc[i][j]; qj[j] += acc[i][j]*acc[i][j];
            mxv[j] = fmaxf(mxv[j], acc[i][j]);
            mnv[j] = fminf(mnv[j], acc[i][j]);
        }
    __syncthreads();
    float* red = Xs;   // overlay: [4][16][128] = S, Q, MX, MN (32 KB)
    {
        float4 a0 = {sj[0], sj[1], sj[2], sj[3]};
        float4 a1 = {sj[4], sj[5], sj[6], sj[7]};
        float4 q0 = {qj[0], qj[1], qj[2], qj[3]};
        float4 q1 = {qj[4], qj[5], qj[6], qj[7]};
        float4 m0 = {mxv[0], mxv[1], mxv[2], mxv[3]};
        float4 m1 = {mxv[4], mxv[5], mxv[6], mxv[7]};
        float4 n0 = {mnv[0], mnv[1], mnv[2], mnv[3]};
        float4 n1 = {mnv[4], mnv[5], mnv[6], mnv[7]};
        *(float4*)(red + pgg*128 + o) = a0;
        *(float4*)(red + pgg*128 + o + 4) = a1;
        *(float4*)(red + 2048 + pgg*128 + o) = q0;
        *(float4*)(red + 2048 + pgg*128 + o + 4) = q1;
        *(float4*)(red + 4096 + pgg*128 + o) = m0;
        *(float4*)(red + 4096 + pgg*128 + o + 4) = m1;
        *(float4*)(red + 6144 + pgg*128 + o) = n0;
        *(float4*)(red + 6144 + pgg*128 + o + 4) = n1;
    }
    __syncthreads();
    if (tid < 128) {
        float S = 0.f, Q = 0.f;
#pragma unroll
        for (int g = 0; g < 16; ++g) { S += red[g*128 + tid]; Q += red[2048 + g*128 + tid]; }
        atomicAdd(&g_stat3[tid], S);
        atomicAdd(&g_stat3[128 + tid], Q);
    }
#pragma unroll
    for (int t = tid; t < 512; t += 256) {
        int g4 = t >> 7, o2 = t & 127;
        float m = red[4096 + (g4*4)*128 + o2];
        float n2 = red[6144 + (g4*4)*128 + o2];
#pragma unroll
        for (int k = 1; k < 4; ++k) {
            m = fmaxf(m, red[4096 + (g4*4+k)*128 + o2]);
            n2 = fminf(n2, red[6144 + (g4*4+k)*128 + o2]);
        }
        g_max3[(size_t)o2*BSS + blockIdx.x*4 + g4] = m;
        g_min3[(size_t)o2*BSS + blockIdx.x*4 + g4] = n2;
    }
}

// ---------------- final: BN3 affine on max/min + ReLU ----------------
__global__ void final_kernel(float* __restrict__ out) {
    int idx = blockIdx.x * 256 + threadIdx.x;
    int b = idx >> 16;
    int rem = idx & 65535;
    int o = rem >> 9;
    int s = rem & 511;
    float sc = g_sc3[o], sh = g_sh3[o];
    float mx = g_max3[(size_t)o*BSS + b*512 + s];
    float mn = g_min3[(size_t)o*BSS + b*512 + s];
    float y = (sc >= 0.f) ? fmaf(sc, mx, sh) : fmaf(sc, mn, sh);
    out[BB*3*SS + idx] = fmaxf(y, 0.f);
}

// ---------------- launch ----------------
extern "C" void kernel_launch(void* const* d_in, const int* in_sizes, int n_in,
                              void* d_out, int out_size) {
    (void)in_sizes; (void)n_in; (void)out_size;
    const float* xyz = (const float*)d_in[0];
    const float* pts = (const float*)d_in[1];
    const float* w0  = (const float*)d_in[2];
    const float* b0  = (const float*)d_in[3];
    const float* g0  = (const float*)d_in[4];
    const float* bt0 = (const float*)d_in[5];
    const float* w1  = (const float*)d_in[6];
    const float* b1  = (const float*)d_in[7];
    const float* g1  = (const float*)d_in[8];
    const float* bt1 = (const float*)d_in[9];
    const float* w2  = (const float*)d_in[10];
    const float* b2  = (const float*)d_in[11];
    const float* g2  = (const float*)d_in[12];
    const float* bt2 = (const float*)d_in[13];
    float* out = (float*)d_out;

    const int smem1 = (C0P*O1 + C0P*128)*4;
    const int smem2 = (64*64 + 64*128)*4;
    const int smem3 = (64*128 + 64*128)*4;
    cudaFuncSetAttribute(conv1_kernel, cudaFuncAttributeMaxDynamicSharedMemorySize, smem1);
    cudaFuncSetAttribute(conv2_kernel, cudaFuncAttributeMaxDynamicSharedMemorySize, smem2);
    cudaFuncSetAttribute(conv3_kernel, cudaFuncAttributeMaxDynamicSharedMemorySize, smem3);

    build_fps_kernel<<<16 + BB*NN/256, 256>>>(xyz, pts, out);
    ball_kernel<<<BB*64, 256>>>(xyz, out);
    conv1_kernel<<<PP/128, 256, smem1>>>(w0, b0, out);
    bnfin_kernel<<<1, 128>>>(1, g0, bt0);
    conv2_kernel<<<PP/128, 256, smem2>>>(w1, b1);
    bnfin_kernel<<<1, 128>>>(2, g1, bt1);
    conv3_kernel<<<PP/128, 256, smem3>>>(w2, b2);
    bnfin_kernel<<<1, 128>>>(3, g2, bt2);
    final_kernel<<<BB*O3*SS/256, 256>>>(out);
}

// round 6
// speedup vs baseline: 1.0033x; 1.0033x over previous
#include <cuda_runtime.h>
#include <math.h>

// Problem constants
#define BB 16
#define NN 2048
#define SS 512      // npoint
#define KK 32       // nsample
#define PP (BB*SS*KK)   // 262144 total "points" through the MLP
#define BSS (BB*SS)
#define C0 67
#define C0P 68      // padded input channels
#define O1 64
#define O2 64
#define O3 128

typedef unsigned long long ull_t;

#define FMA2(d, a, b, c) \
    asm("fma.rn.f32x2 %0, %1, %2, %3;" : "=l"(d) : "l"(a), "l"(b), "l"(c))

__device__ __forceinline__ float ull_lo(ull_t v) {
    return __uint_as_float((unsigned)(v & 0xffffffffull));
}
__device__ __forceinline__ float ull_hi(ull_t v) {
    return __uint_as_float((unsigned)(v >> 32));
}
__device__ __forceinline__ ull_t dup2(float v) {
    unsigned u = __float_as_uint(v);
    ull_t r;
    asm("mov.b64 %0, {%1, %1};" : "=l"(r) : "r"(u));
    return r;
}

// ---------------- scratch ----------------
static __device__ __align__(16) float g_featT[BB*NN*C0P];         // 8.9 MB  [b][n][c]
static __device__ int   g_bidx[PP];                               // ball-query indices
static __device__ __align__(16) float g_bufA[(size_t)O1*PP];      // 67 MB   (conv1 out)
static __device__ __align__(16) float g_bufB[(size_t)O2*PP];      // 67 MB   (conv2 out)
static __device__ __align__(16) float g_max3[(size_t)O3*BSS];     // 4 MB
static __device__ __align__(16) float g_min3[(size_t)O3*BSS];     // 4 MB
static __device__ float g_stat1[2*O1], g_stat2[2*O2], g_stat3[2*O3];

__device__ __forceinline__ void bn_coeff(const float* stat, int C, int o,
                                         const float* g, const float* bt,
                                         float& sc, float& sh) {
    const float invN = 1.f / (float)PP;
    float mean = stat[o] * invN;
    float var = fmaxf(stat[C + o] * invN - mean*mean, 0.f);
    float is = rsqrtf(var + 1e-5f);
    float s = g[o] * is;
    sc = s;
    sh = fmaf(-mean, s, bt[o]);
}

// ---------------- fused: blocks 0..15 = FPS (one per batch), 16..143 = build featT ----------------
__global__ __launch_bounds__(256)
void build_fps_kernel(const float* __restrict__ xyz,
                      const float* __restrict__ pts,
                      float* __restrict__ out) {
    __shared__ float sx[NN], sy[NN], sz[NN];
    __shared__ ull_t swk[2][8];
    int tid = threadIdx.x;

    if (blockIdx.x >= 16) {
        // ---------------- build featT ----------------
        if (blockIdx.x == 16) {
            if (tid < 2*O1) g_stat1[tid] = 0.f;
            if (tid < 2*O2) g_stat2[tid] = 0.f;
            if (tid < 2*O3) g_stat3[tid] = 0.f;
        }
        int id = (blockIdx.x - 16) * 256 + tid;   // (b,n) flat, 32768 total
        int b = id >> 11, n = id & 2047;
        const float* xb = xyz + b * 3 * NN;
        const float* pb2 = pts + (size_t)b * 64 * NN;
        float* dst = g_featT + (size_t)id * C0P;
        float4 v;
        v.x = xb[n]; v.y = xb[NN + n]; v.z = xb[2*NN + n]; v.w = pb2[n];
        ((float4*)dst)[0] = v;
#pragma unroll
        for (int g = 1; g < 17; ++g) {
            int ch = 4*g - 3;
            v.x = pb2[(ch+0)*NN + n];
            v.y = pb2[(ch+1)*NN + n];
            v.z = pb2[(ch+2)*NN + n];
            v.w = (4*g + 3 < C0) ? pb2[(ch+3)*NN + n] : 0.f;
            ((float4*)dst)[g] = v;
        }
        return;
    }

    // ---------------- FPS ----------------
    int b = blockIdx.x;
    const float* xb = xyz + b * 3 * NN;
    int lane = tid & 31, wid = tid >> 5;
    for (int i = tid; i < NN; i += 256) {
        sx[i] = xb[i]; sy[i] = xb[NN + i]; sz[i] = xb[2*NN + i];
    }
    __syncthreads();
    float px[8], py[8], pz[8], dist[8];
#pragma unroll
    for (int i = 0; i < 8; ++i) {
        int n = tid + i*256;
        px[i] = sx[n]; py[i] = sy[n]; pz[i] = sz[n];
        dist[i] = 1e10f;
    }
    int far = 0, pb = 0;
    float* ob = out + b * 3 * SS;
    for (int it = 0; it < SS; ++it) {
        float cx = sx[far], cy = sy[far], cz = sz[far];
        if (tid == 0) { ob[it] = cx; ob[SS+it] = cy; ob[2*SS+it] = cz; }
        unsigned bb = 0u; unsigned bi = 0xffffffffu;
#pragma unroll
        for (int i = 0; i < 8; ++i) {
            float dx = px[i]-cx, dy = py[i]-cy, dz = pz[i]-cz;
            float d = dx*dx; d += dy*dy; d += dz*dz;
            float dd = fminf(dist[i], d); dist[i] = dd;
            unsigned bits = __float_as_uint(dd);   // monotone for dd >= 0
            if (bits > bb) { bb = bits; bi = (unsigned)(tid + i*256); }
        }
        unsigned wm = __reduce_max_sync(0xffffffffu, bb);
        unsigned cand = (bb == wm) ? bi : 0xffffffffu;
        unsigned wi = __reduce_min_sync(0xffffffffu, cand);   // first-index tie-break
        if (lane == 0) swk[pb][wid] = ((ull_t)wm << 32) | (unsigned)(~wi);
        __syncthreads();
        // every thread scalar-maxes the 8 staged packed keys (broadcast LDS.64)
        ull_t k = swk[pb][0];
#pragma unroll
        for (int i2 = 1; i2 < 8; ++i2) {
            ull_t k2 = swk[pb][i2];
            if (k2 > k) k = k2;
        }
        far = (int)(~(unsigned)k);
        pb ^= 1;
    }
}

// ---------------- ball query: smem-staged xyz; warp per center ----------------
__global__ __launch_bounds__(256)
void ball_kernel(const float* __restrict__ xyz,
                 const float* __restrict__ newxyz /* = d_out head */) {
    __shared__ float sx[NN], sy[NN], sz[NN];
    int b = blockIdx.x >> 6, schunk = blockIdx.x & 63;
    const float* xb = xyz + b * 3 * NN;
    for (int i = threadIdx.x; i < NN; i += 256) {
        sx[i] = xb[i]; sy[i] = xb[NN + i]; sz[i] = xb[2*NN + i];
    }
    __syncthreads();
    int w = threadIdx.x >> 5, lane = threadIdx.x & 31;
    int s = schunk * 8 + w;
    float cx = newxyz[b*3*SS + s];
    float cy = newxyz[b*3*SS + SS + s];
    float cz = newxyz[b*3*SS + 2*SS + s];
    int* dst = g_bidx + (b*SS + s) * KK;
    const float R2 = 0.04f;
    int count = 0, first = -1;
    for (int r = 0; r < NN/32; ++r) {
        int n = r*32 + lane;
        float dx = cx - sx[n], dy = cy - sy[n], dz = cz - sz[n];
        float d = dx*dx; d += dy*dy; d += dz*dz;
        bool q = (d <= R2);
        unsigned m = __ballot_sync(0xffffffffu, q);
        if (first < 0 && m) first = r*32 + __ffs(m) - 1;
        int pos = count + __popc(m & ((1u << lane) - 1u));
        if (q && pos < KK) dst[pos] = n;
        count += __popc(m);
        if (count >= KK) break;
    }
    if (count < KK && lane >= count && lane < KK) dst[lane] = first;
}

// ---------------- conv1: gather + GEMM(67->64) f32x2 (reg-dup W) + bias + BN stats ----------------
__global__ __launch_bounds__(256)
void conv1_kernel(const float* __restrict__ w0, const float* __restrict__ b0,
                  const float* __restrict__ newxyz) {
    extern __shared__ float sm[];
    float* Ws = sm;                 // [68][64] compact
    float* Xs = sm + C0P * O1;      // [68][128]
    int tid = threadIdx.x, lane = tid & 31, w = tid >> 5;
    int pbase = blockIdx.x * 128;

    // W load (compact, pad rows zeroed)
    {
        int o = tid & 63, cq = tid >> 6;
#pragma unroll
        for (int k = 0; k < 17; ++k) {
            int c = cq*17 + k;
            Ws[c*64 + o] = (c < C0) ? w0[o*C0 + c] : 0.f;
        }
    }
    // X gather
    {
        int pg = w & 3, half = w >> 2;
        int p = pg*32 + lane;
        int gp = pbase + p;
        int n = g_bidx[gp];
        int sg = gp >> 5;
        int bbt = sg >> 9, ss = sg & 511;
        const float* row = g_featT + ((size_t)(bbt*NN + n)) * C0P;
        float ccx = 0.f, ccy = 0.f, ccz = 0.f;
        if (half == 0) {
            ccx = newxyz[bbt*3*SS + ss];
            ccy = newxyz[bbt*3*SS + SS + ss];
            ccz = newxyz[bbt*3*SS + 2*SS + ss];
        }
        int ga = half ? 9 : 0, gb = half ? 17 : 9;
        for (int g = ga; g < gb; ++g) {
            float4 v = ((const float4*)row)[g];
            if (g == 0) { v.x -= ccx; v.y -= ccy; v.z -= ccz; }
            Xs[(4*g+0)*128 + p] = v.x;
            Xs[(4*g+1)*128 + p] = v.y;
            Xs[(4*g+2)*128 + p] = v.z;
            Xs[(4*g+3)*128 + p] = v.w;
        }
    }
    __syncthreads();

    int og = tid & 15, o = og*4;
    int pgg = tid >> 4, pp = pgg*8;
    ull_t accp[4][4];
#pragma unroll
    for (int i = 0; i < 4; ++i)
#pragma unroll
        for (int j = 0; j < 4; ++j) accp[i][j] = 0ull;

#pragma unroll 4
    for (int c = 0; c < C0P; ++c) {
        ulonglong2 xa = *(const ulonglong2*)(Xs + c*128 + pp);
        ulonglong2 xb2 = *(const ulonglong2*)(Xs + c*128 + pp + 4);
        float4 wv = *(const float4*)(Ws + c*64 + o);
        ull_t xs[4] = {xa.x, xa.y, xb2.x, xb2.y};
        ull_t ws[4] = {dup2(wv.x), dup2(wv.y), dup2(wv.z), dup2(wv.w)};
#pragma unroll
        for (int i = 0; i < 4; ++i)
#pragma unroll
            for (int j = 0; j < 4; ++j)
                FMA2(accp[i][j], xs[i], ws[j], accp[i][j]);
    }
    // unpack (bit-exact vs scalar)
    float acc[8][4];
#pragma unroll
    for (int i = 0; i < 4; ++i)
#pragma unroll
        for (int j = 0; j < 4; ++j) {
            acc[2*i][j] = ull_lo(accp[i][j]);
            acc[2*i+1][j] = ull_hi(accp[i][j]);
        }
    float4 bias = *(const float4*)(b0 + o);
    float bv[4] = {bias.x, bias.y, bias.z, bias.w};
#pragma unroll
    for (int i = 0; i < 8; ++i)
#pragma unroll
        for (int j = 0; j < 4; ++j) acc[i][j] += bv[j];

#pragma unroll
    for (int j = 0; j < 4; ++j) {
        float* dst = g_bufA + (size_t)(o+j)*PP + pbase + pp;
        float4 u0 = {acc[0][j], acc[1][j], acc[2][j], acc[3][j]};
        float4 u1 = {acc[4][j], acc[5][j], acc[6][j], acc[7][j]};
        ((float4*)dst)[0] = u0; ((float4*)dst)[1] = u1;
    }
    float sj[4] = {0,0,0,0}, qj[4] = {0,0,0,0};
#pragma unroll
    for (int i = 0; i < 8; ++i)
#pragma unroll
        for (int j = 0; j < 4; ++j) { sj[j] += acc[i][j]; qj[j] += acc[i][j]*acc[i][j]; }
    __syncthreads();
    float* red = Xs;   // overlay: [2][16][64]
    {
        float4 a = {sj[0], sj[1], sj[2], sj[3]};
        float4 b2 = {qj[0], qj[1], qj[2], qj[3]};
        *(float4*)(red + pgg*64 + o) = a;
        *(float4*)(red + 1024 + pgg*64 + o) = b2;
    }
    __syncthreads();
    if (tid < 64) {
        float S = 0.f, Q = 0.f;
#pragma unroll
        for (int g = 0; g < 16; ++g) { S += red[g*64 + tid]; Q += red[1024 + g*64 + tid]; }
        atomicAdd(&g_stat1[tid], S);
        atomicAdd(&g_stat1[64 + tid], Q);
    }
}

// ---------------- conv2: BN1 coeff in-block + BN1+ReLU on load, GEMM(64->64) f32x2 ----------------
__global__ __launch_bounds__(256)
void conv2_kernel(const float* __restrict__ w1, const float* __restrict__ b1,
                  const float* __restrict__ g0, const float* __restrict__ bt0) {
    extern __shared__ float sm[];
    float* Ws = sm;                 // [64][64]
    float* Xs = sm + 64*64;         // [64][128]
    float* sc1 = Xs + 64*128;       // [64]
    float* sh1 = sc1 + 64;          // [64]
    int tid = threadIdx.x, lane = tid & 31, w = tid >> 5;
    int pbase = blockIdx.x * 128;
    if (tid < 64) {
        float sc, sh;
        bn_coeff(g_stat1, O1, tid, g0, bt0, sc, sh);
        sc1[tid] = sc; sh1[tid] = sh;
    }
    {
        int o = tid & 63, cq = tid >> 6;
#pragma unroll
        for (int k = 0; k < 16; ++k) {
            int c = cq*16 + k;
            Ws[c*64 + o] = w1[o*64 + c];
        }
    }
    __syncthreads();
    for (int c = w; c < 64; c += 8) {
        float sc = sc1[c], sh = sh1[c];
        float4 v = *(const float4*)(g_bufA + (size_t)c*PP + pbase + lane*4);
        v.x = fmaxf(fmaf(v.x, sc, sh), 0.f);
        v.y = fmaxf(fmaf(v.y, sc, sh), 0.f);
        v.z = fmaxf(fmaf(v.z, sc, sh), 0.f);
        v.w = fmaxf(fmaf(v.w, sc, sh), 0.f);
        *(float4*)(Xs + c*128 + lane*4) = v;
    }
    __syncthreads();

    int og = tid & 15, o = og*4;
    int pgg = tid >> 4, pp = pgg*8;
    ull_t accp[4][4];
#pragma unroll
    for (int i = 0; i < 4; ++i)
#pragma unroll
        for (int j = 0; j < 4; ++j) accp[i][j] = 0ull;
#pragma unroll 4
    for (int c = 0; c < 64; ++c) {
        ulonglong2 xa = *(const ulonglong2*)(Xs + c*128 + pp);
        ulonglong2 xb2 = *(const ulonglong2*)(Xs + c*128 + pp + 4);
        float4 wv = *(const float4*)(Ws + c*64 + o);
        ull_t xs[4] = {xa.x, xa.y, xb2.x, xb2.y};
        ull_t ws[4] = {dup2(wv.x), dup2(wv.y), dup2(wv.z), dup2(wv.w)};
#pragma unroll
        for (int i = 0; i < 4; ++i)
#pragma unroll
            for (int j = 0; j < 4; ++j)
                FMA2(accp[i][j], xs[i], ws[j], accp[i][j]);
    }
    float acc[8][4];
#pragma unroll
    for (int i = 0; i < 4; ++i)
#pragma unroll
        for (int j = 0; j < 4; ++j) {
            acc[2*i][j] = ull_lo(accp[i][j]);
            acc[2*i+1][j] = ull_hi(accp[i][j]);
        }
    float4 bias = *(const float4*)(b1 + o);
    float bv[4] = {bias.x, bias.y, bias.z, bias.w};
#pragma unroll
    for (int i = 0; i < 8; ++i)
#pragma unroll
        for (int j = 0; j < 4; ++j) acc[i][j] += bv[j];
#pragma unroll
    for (int j = 0; j < 4; ++j) {
        float* dst = g_bufB + (size_t)(o+j)*PP + pbase + pp;
        float4 u0 = {acc[0][j], acc[1][j], acc[2][j], acc[3][j]};
        float4 u1 = {acc[4][j], acc[5][j], acc[6][j], acc[7][j]};
        ((float4*)dst)[0] = u0; ((float4*)dst)[1] = u1;
    }
    float sj[4] = {0,0,0,0}, qj[4] = {0,0,0,0};
#pragma unroll
    for (int i = 0; i < 8; ++i)
#pragma unroll
        for (int j = 0; j < 4; ++j) { sj[j] += acc[i][j]; qj[j] += acc[i][j]*acc[i][j]; }
    __syncthreads();
    float* red = Xs;
    {
        float4 a = {sj[0], sj[1], sj[2], sj[3]};
        float4 b2 = {qj[0], qj[1], qj[2], qj[3]};
        *(float4*)(red + pgg*64 + o) = a;
        *(float4*)(red + 1024 + pgg*64 + o) = b2;
    }
    __syncthreads();
    if (tid < 64) {
        float S = 0.f, Q = 0.f;
#pragma unroll
        for (int g = 0; g < 16; ++g) { S += red[g*64 + tid]; Q += red[1024 + g*64 + tid]; }
        atomicAdd(&g_stat2[tid], S);
        atomicAdd(&g_stat2[64 + tid], Q);
    }
}

// ---------------- conv3: BN2 coeff in-block + BN2+ReLU on load, GEMM(64->128) f32x2, fused max/min ----------------
__global__ __launch_bounds__(256)
void conv3_kernel(const float* __restrict__ w2, const float* __restrict__ b2p,
                  const float* __restrict__ g1, const float* __restrict__ bt1) {
    extern __shared__ float sm[];
    float* Ws = sm;                 // [64][128]
    float* Xs = sm + 64*128;        // [64][128]
    float* sc2 = Xs + 64*128;       // [64]
    float* sh2 = sc2 + 64;          // [64]
    int tid = threadIdx.x, lane = tid & 31, w = tid >> 5;
    int pbase = blockIdx.x * 128;
    if (tid < 64) {
        float sc, sh;
        bn_coeff(g_stat2, O2, tid, g1, bt1, sc, sh);
        sc2[tid] = sc; sh2[tid] = sh;
    }
    {
        int o = tid & 127, ch = tid >> 7;
#pragma unroll
        for (int cc = 0; cc < 32; ++cc) {
            int c = ch*32 + cc;
            Ws[c*128 + o] = w2[o*64 + c];
        }
    }
    __syncthreads();
    for (int c = w; c < 64; c += 8) {
        float sc = sc2[c], sh = sh2[c];
        float4 v = *(const float4*)(g_bufB + (size_t)c*PP + pbase + lane*4);
        v.x = fmaxf(fmaf(v.x, sc, sh), 0.f);
        v.y = fmaxf(fmaf(v.y, sc, sh), 0.f);
        v.z = fmaxf(fmaf(v.z, sc, sh), 0.f);
        v.w = fmaxf(fmaf(v.w, sc, sh), 0.f);
        *(float4*)(Xs + c*128 + lane*4) = v;
    }
    __syncthreads();

    int og = tid & 15, o = og*8;
    int pgg = tid >> 4, pp = pgg*8;
    ull_t accp[4][8];
#pragma unroll
    for (int i = 0; i < 4; ++i)
#pragma unroll
        for (int j = 0; j < 8; ++j) accp[i][j] = 0ull;
#pragma unroll 2
    for (int c = 0; c < 64; ++c) {
        ulonglong2 xa = *(const ulonglong2*)(Xs + c*128 + pp);
        ulonglong2 xb2 = *(const ulonglong2*)(Xs + c*128 + pp + 4);
        float4 wa = *(const float4*)(Ws + c*128 + o);
        float4 wb = *(const float4*)(Ws + c*128 + o + 4);
        ull_t xs[4] = {xa.x, xa.y, xb2.x, xb2.y};
        ull_t ws[8] = {dup2(wa.x), dup2(wa.y), dup2(wa.z), dup2(wa.w),
                       dup2(wb.x), dup2(wb.y), dup2(wb.z), dup2(wb.w)};
#pragma unroll
        for (int i = 0; i < 4; ++i)
#pragma unroll
            for (int j = 0; j < 8; ++j)
                FMA2(accp[i][j], xs[i], ws[j], accp[i][j]);
    }
    float acc[8][8];
#pragma unroll
    for (int i = 0; i < 4; ++i)
#pragma unroll
        for (int j = 0; j < 8; ++j) {
            acc[2*i][j] = ull_lo(accp[i][j]);
            acc[2*i+1][j] = ull_hi(accp[i][j]);
        }
    float4 ba = *(const float4*)(b2p + o);
    float4 bbv = *(const float4*)(b2p + o + 4);
    float bv[8] = {ba.x, ba.y, ba.z, ba.w, bbv.x, bbv.y, bbv.z, bbv.w};
#pragma unroll
    for (int i = 0; i < 8; ++i)
#pragma unroll
        for (int j = 0; j < 8; ++j) acc[i][j] += bv[j];

    float sj[8], qj[8], mxv[8], mnv[8];
#pragma unroll
    for (int j = 0; j < 8; ++j) {
        sj[j] = acc[0][j]; qj[j] = acc[0][j]*acc[0][j];
        mxv[j] = acc[0][j]; mnv[j] = acc[0][j];
    }
#pragma unroll
    for (int i = 1; i < 8; ++i)
#pragma unroll
        for (int j = 0; j < 8; ++j) {
            sj[j] += acc[i][j]; qj[j] += acc[i][j]*acc[i][j];
            mxv[j] = fmaxf(mxv[j], acc[i][j]);
            mnv[j] = fminf(mnv[j], acc[i][j]);
        }
    __syncthreads();
    float* red = Xs;   // overlay: [4][16][128] = S, Q, MX, MN (32 KB)
    {
        float4 a0 = {sj[0], sj[1], sj[2], sj[3]};
        float4 a1 = {sj[4], sj[5], sj[6], sj[7]};
        float4 q0 = {qj[0], qj[1], qj[2], qj[3]};
        float4 q1 = {qj[4], qj[5], qj[6], qj[7]};
        float4 m0 = {mxv[0], mxv[1], mxv[2], mxv[3]};
        float4 m1 = {mxv[4], mxv[5], mxv[6], mxv[7]};
        float4 n0 = {mnv[0], mnv[1], mnv[2], mnv[3]};
        float4 n1 = {mnv[4], mnv[5], mnv[6], mnv[7]};
        *(float4*)(red + pgg*128 + o) = a0;
        *(float4*)(red + pgg*128 + o + 4) = a1;
        *(float4*)(red + 2048 + pgg*128 + o) = q0;
        *(float4*)(red + 2048 + pgg*128 + o + 4) = q1;
        *(float4*)(red + 4096 + pgg*128 + o) = m0;
        *(float4*)(red + 4096 + pgg*128 + o + 4) = m1;
        *(float4*)(red + 6144 + pgg*128 + o) = n0;
        *(float4*)(red + 6144 + pgg*128 + o + 4) = n1;
    }
    __syncthreads();
    if (tid < 128) {
        float S = 0.f, Q = 0.f;
#pragma unroll
        for (int g = 0; g < 16; ++g) { S += red[g*128 + tid]; Q += red[2048 + g*128 + tid]; }
        atomicAdd(&g_stat3[tid], S);
        atomicAdd(&g_stat3[128 + tid], Q);
    }
#pragma unroll
    for (int t = tid; t < 512; t += 256) {
        int g4 = t >> 7, o2 = t & 127;
        float m = red[4096 + (g4*4)*128 + o2];
        float n2 = red[6144 + (g4*4)*128 + o2];
#pragma unroll
        for (int k = 1; k < 4; ++k) {
            m = fmaxf(m, red[4096 + (g4*4+k)*128 + o2]);
            n2 = fminf(n2, red[6144 + (g4*4+k)*128 + o2]);
        }
        g_max3[(size_t)o2*BSS + blockIdx.x*4 + g4] = m;
        g_min3[(size_t)o2*BSS + blockIdx.x*4 + g4] = n2;
    }
}

// ---------------- final: BN3 coeff per-thread + affine on max/min + ReLU ----------------
__global__ void final_kernel(float* __restrict__ out,
                             const float* __restrict__ g2,
                             const float* __restrict__ bt2) {
    int idx = blockIdx.x * 256 + threadIdx.x;
    int b = idx >> 16;
    int rem = idx & 65535;
    int o = rem >> 9;
    int s = rem & 511;
    float sc, sh;
    bn_coeff(g_stat3, O3, o, g2, bt2, sc, sh);
    float mx = g_max3[(size_t)o*BSS + b*512 + s];
    float mn = g_min3[(size_t)o*BSS + b*512 + s];
    float y = (sc >= 0.f) ? fmaf(sc, mx, sh) : fmaf(sc, mn, sh);
    out[BB*3*SS + idx] = fmaxf(y, 0.f);
}

// ---------------- launch ----------------
extern "C" void kernel_launch(void* const* d_in, const int* in_sizes, int n_in,
                              void* d_out, int out_size) {
    (void)in_sizes; (void)n_in; (void)out_size;
    const float* xyz = (const float*)d_in[0];
    const float* pts = (const float*)d_in[1];
    const float* w0  = (const float*)d_in[2];
    const float* b0  = (const float*)d_in[3];
    const float* g0  = (const float*)d_in[4];
    const float* bt0 = (const float*)d_in[5];
    const float* w1  = (const float*)d_in[6];
    const float* b1  = (const float*)d_in[7];
    const float* g1  = (const float*)d_in[8];
    const float* bt1 = (const float*)d_in[9];
    const float* w2  = (const float*)d_in[10];
    const float* b2  = (const float*)d_in[11];
    const float* g2  = (const float*)d_in[12];
    const float* bt2 = (const float*)d_in[13];
    float* out = (float*)d_out;

    const int smem1 = (C0P*O1 + C0P*128)*4;
    const int smem2 = (64*64 + 64*128 + 128)*4;
    const int smem3 = (64*128 + 64*128 + 128)*4;
    cudaFuncSetAttribute(conv1_kernel, cudaFuncAttributeMaxDynamicSharedMemorySize, smem1);
    cudaFuncSetAttribute(conv2_kernel, cudaFuncAttributeMaxDynamicSharedMemorySize, smem2);
    cudaFuncSetAttribute(conv3_kernel, cudaFuncAttributeMaxDynamicSharedMemorySize, smem3);

    build_fps_kernel<<<16 + BB*NN/256, 256>>>(xyz, pts, out);
    ball_kernel<<<BB*64, 256>>>(xyz, out);
    conv1_kernel<<<PP/128, 256, smem1>>>(w0, b0, out);
    conv2_kernel<<<PP/128, 256, smem2>>>(w1, b1, g0, bt0);
    conv3_kernel<<<PP/128, 256, smem3>>>(w2, b2, g1, bt1);
    final_kernel<<<BB*O3*SS/256, 256>>>(out, g2, bt2);
}

// round 7
// speedup vs baseline: 1.0927x; 1.0892x over previous
#include <cuda_runtime.h>
#include <math.h>

// Problem constants
#define BB 16
#define NN 2048
#define SS 512      // npoint
#define KK 32       // nsample
#define PP (BB*SS*KK)   // 262144 total "points" through the MLP
#define BSS (BB*SS)
#define C0 67
#define C0P 68      // padded input channels
#define O1 64
#define O2 64
#define O3 128

typedef unsigned long long ull_t;

#define FMA2(d, a, b, c) \
    asm("fma.rn.f32x2 %0, %1, %2, %3;" : "=l"(d) : "l"(a), "l"(b), "l"(c))

__device__ __forceinline__ float ull_lo(ull_t v) {
    return __uint_as_float((unsigned)(v & 0xffffffffull));
}
__device__ __forceinline__ float ull_hi(ull_t v) {
    return __uint_as_float((unsigned)(v >> 32));
}
__device__ __forceinline__ ull_t dup2(float v) {
    unsigned u = __float_as_uint(v);
    ull_t r;
    asm("mov.b64 %0, {%1, %1};" : "=l"(r) : "r"(u));
    return r;
}

// ---------------- scratch ----------------
static __device__ __align__(16) float g_featT[BB*NN*C0P];         // 8.9 MB  [b][n][c]
static __device__ int   g_bidx[PP];                               // ball-query indices
static __device__ __align__(16) float g_bufA[(size_t)O1*PP];      // 67 MB   (conv1 out)
static __device__ __align__(16) float g_bufB[(size_t)O2*PP];      // 67 MB   (conv2 out)
static __device__ __align__(16) float g_max3[(size_t)O3*BSS];     // 4 MB
static __device__ __align__(16) float g_min3[(size_t)O3*BSS];     // 4 MB
static __device__ float g_stat1[2*O1], g_stat2[2*O2], g_stat3[2*O3];

__device__ __forceinline__ void bn_coeff(const float* stat, int C, int o,
                                         const float* g, const float* bt,
                                         float& sc, float& sh) {
    const float invN = 1.f / (float)PP;
    float mean = stat[o] * invN;
    float var = fmaxf(stat[C + o] * invN - mean*mean, 0.f);
    float is = rsqrtf(var + 1e-5f);
    float s = g[o] * is;
    sc = s;
    sh = fmaf(-mean, s, bt[o]);
}

// ---------------- build featT (+ zero BN stats in block 0) ----------------
__global__ void build_feat_kernel(const float* __restrict__ xyz,
                                  const float* __restrict__ pts) {
    if (blockIdx.x == 0) {
        int t = threadIdx.x;
        if (t < 2*O1) g_stat1[t] = 0.f;
        if (t < 2*O2) g_stat2[t] = 0.f;
        if (t < 2*O3) g_stat3[t] = 0.f;
    }
    int id = blockIdx.x * 256 + threadIdx.x;   // (b,n) flat, 32768 total
    int b = id >> 11, n = id & 2047;
    const float* xb = xyz + b * 3 * NN;
    const float* pb = pts + (size_t)b * 64 * NN;
    float* dst = g_featT + (size_t)id * C0P;
    float4 v;
    v.x = xb[n]; v.y = xb[NN + n]; v.z = xb[2*NN + n]; v.w = pb[n];
    ((float4*)dst)[0] = v;
#pragma unroll
    for (int g = 1; g < 17; ++g) {
        int ch = 4*g - 3;
        v.x = pb[(ch+0)*NN + n];
        v.y = pb[(ch+1)*NN + n];
        v.z = pb[(ch+2)*NN + n];
        v.w = (4*g + 3 < C0) ? pb[(ch+3)*NN + n] : 0.f;
        ((float4*)dst)[g] = v;
    }
}

// ---------------- FPS: one block/batch, 256 thr x 8 pts, REDUX argmax, 1 barrier/iter ----------------
__global__ __launch_bounds__(256)
void fps_kernel(const float* __restrict__ xyz, float* __restrict__ out) {
    __shared__ float sx[NN], sy[NN], sz[NN];
    __shared__ unsigned swb[2][8], swi[2][8];
    int b = blockIdx.x;
    const float* xb = xyz + b * 3 * NN;
    int tid = threadIdx.x, lane = tid & 31, wid = tid >> 5;
    for (int i = tid; i < NN; i += 256) {
        sx[i] = xb[i]; sy[i] = xb[NN + i]; sz[i] = xb[2*NN + i];
    }
    __syncthreads();
    float px[8], py[8], pz[8], dist[8];
#pragma unroll
    for (int i = 0; i < 8; ++i) {
        int n = tid + i*256;
        px[i] = sx[n]; py[i] = sy[n]; pz[i] = sz[n];
        dist[i] = 1e10f;
    }
    int far = 0, pb = 0;
    float* ob = out + b * 3 * SS;
    for (int it = 0; it < SS; ++it) {
        float cx = sx[far], cy = sy[far], cz = sz[far];
        if (tid == 0) { ob[it] = cx; ob[SS+it] = cy; ob[2*SS+it] = cz; }
        unsigned bb = 0u; unsigned bi = 0xffffffffu;
#pragma unroll
        for (int i = 0; i < 8; ++i) {
            float dx = px[i]-cx, dy = py[i]-cy, dz = pz[i]-cz;
            float d = dx*dx; d += dy*dy; d += dz*dz;
            float dd = fminf(dist[i], d); dist[i] = dd;
            unsigned bits = __float_as_uint(dd);   // monotone for dd >= 0
            if (bits > bb) { bb = bits; bi = (unsigned)(tid + i*256); }
        }
        unsigned wm = __reduce_max_sync(0xffffffffu, bb);
        unsigned cand = (bb == wm) ? bi : 0xffffffffu;
        unsigned wi = __reduce_min_sync(0xffffffffu, cand);   // first-index tie-break
        if (lane == 0) { swb[pb][wid] = wm; swi[pb][wid] = wi; }
        __syncthreads();
        // every warp redundantly reduces the 8 staged values (replication-safe)
        unsigned b2 = swb[pb][lane & 7];
        unsigned i2 = swi[pb][lane & 7];
        unsigned m2 = __reduce_max_sync(0xffffffffu, b2);
        unsigned c2 = (b2 == m2) ? i2 : 0xffffffffu;
        far = (int)__reduce_min_sync(0xffffffffu, c2);
        pb ^= 1;
    }
}

// ---------------- ball query: smem-staged xyz; warp per center ----------------
__global__ __launch_bounds__(256)
void ball_kernel(const float* __restrict__ xyz,
                 const float* __restrict__ newxyz /* = d_out head */) {
    __shared__ float sx[NN], sy[NN], sz[NN];
    int b = blockIdx.x >> 6, schunk = blockIdx.x & 63;
    const float* xb = xyz + b * 3 * NN;
    for (int i = threadIdx.x; i < NN; i += 256) {
        sx[i] = xb[i]; sy[i] = xb[NN + i]; sz[i] = xb[2*NN + i];
    }
    __syncthreads();
    int w = threadIdx.x >> 5, lane = threadIdx.x & 31;
    int s = schunk * 8 + w;
    float cx = newxyz[b*3*SS + s];
    float cy = newxyz[b*3*SS + SS + s];
    float cz = newxyz[b*3*SS + 2*SS + s];
    int* dst = g_bidx + (b*SS + s) * KK;
    const float R2 = 0.04f;
    int count = 0, first = -1;
    for (int r = 0; r < NN/32; ++r) {
        int n = r*32 + lane;
        float dx = cx - sx[n], dy = cy - sy[n], dz = cz - sz[n];
        float d = dx*dx; d += dy*dy; d += dz*dz;
        bool q = (d <= R2);
        unsigned m = __ballot_sync(0xffffffffu, q);
        if (first < 0 && m) first = r*32 + __ffs(m) - 1;
        int pos = count + __popc(m & ((1u << lane) - 1u));
        if (q && pos < KK) dst[pos] = n;
        count += __popc(m);
        if (count >= KK) break;
    }
    if (count < KK && lane >= count && lane < KK) dst[lane] = first;
}

// ---------------- conv1: gather (batched loads) + GEMM(67->64) f32x2 + bias + BN stats ----------------
__global__ __launch_bounds__(256)
void conv1_kernel(const float* __restrict__ w0, const float* __restrict__ b0,
                  const float* __restrict__ newxyz) {
    extern __shared__ float sm[];
    float* Ws = sm;                 // [68][64] compact
    float* Xs = sm + C0P * O1;      // [68][128]
    int tid = threadIdx.x, lane = tid & 31, w = tid >> 5;
    int pbase = blockIdx.x * 128;

    // W load (compact, pad rows zeroed)
    {
        int o = tid & 63, cq = tid >> 6;
#pragma unroll
        for (int k = 0; k < 17; ++k) {
            int c = cq*17 + k;
            Ws[c*64 + o] = (c < C0) ? w0[o*C0 + c] : 0.f;
        }
    }
    // X gather: batched loads first (MLP), then stores
    {
        int pg = w & 3, half = w >> 2;
        int p = pg*32 + lane;
        int gp = pbase + p;
        int n = g_bidx[gp];
        int sg = gp >> 5;
        int bbt = sg >> 9, ss = sg & 511;
        const float* row = g_featT + ((size_t)(bbt*NN + n)) * C0P;
        if (half == 0) {
            float4 v[9];
#pragma unroll
            for (int g = 0; g < 9; ++g) v[g] = ((const float4*)row)[g];
            float ccx = newxyz[bbt*3*SS + ss];
            float ccy = newxyz[bbt*3*SS + SS + ss];
            float ccz = newxyz[bbt*3*SS + 2*SS + ss];
            v[0].x -= ccx; v[0].y -= ccy; v[0].z -= ccz;
#pragma unroll
            for (int g = 0; g < 9; ++g) {
                Xs[(4*g+0)*128 + p] = v[g].x;
                Xs[(4*g+1)*128 + p] = v[g].y;
                Xs[(4*g+2)*128 + p] = v[g].z;
                Xs[(4*g+3)*128 + p] = v[g].w;
            }
        } else {
            float4 v[8];
#pragma unroll
            for (int g = 0; g < 8; ++g) v[g] = ((const float4*)row)[g + 9];
#pragma unroll
            for (int g = 0; g < 8; ++g) {
                int gg = g + 9;
                Xs[(4*gg+0)*128 + p] = v[g].x;
                Xs[(4*gg+1)*128 + p] = v[g].y;
                Xs[(4*gg+2)*128 + p] = v[g].z;
                Xs[(4*gg+3)*128 + p] = v[g].w;
            }
        }
    }
    __syncthreads();

    int og = tid & 15, o = og*4;
    int pgg = tid >> 4, pp = pgg*8;
    ull_t accp[4][4];
#pragma unroll
    for (int i = 0; i < 4; ++i)
#pragma unroll
        for (int j = 0; j < 4; ++j) accp[i][j] = 0ull;

#pragma unroll 4
    for (int c = 0; c < C0P; ++c) {
        ulonglong2 xa = *(const ulonglong2*)(Xs + c*128 + pp);
        ulonglong2 xb2 = *(const ulonglong2*)(Xs + c*128 + pp + 4);
        float4 wv = *(const float4*)(Ws + c*64 + o);
        ull_t xs[4] = {xa.x, xa.y, xb2.x, xb2.y};
        ull_t ws[4] = {dup2(wv.x), dup2(wv.y), dup2(wv.z), dup2(wv.w)};
#pragma unroll
        for (int i = 0; i < 4; ++i)
#pragma unroll
            for (int j = 0; j < 4; ++j)
                FMA2(accp[i][j], xs[i], ws[j], accp[i][j]);
    }
    // unpack (bit-exact vs scalar)
    float acc[8][4];
#pragma unroll
    for (int i = 0; i < 4; ++i)
#pragma unroll
        for (int j = 0; j < 4; ++j) {
            acc[2*i][j] = ull_lo(accp[i][j]);
            acc[2*i+1][j] = ull_hi(accp[i][j]);
        }
    float4 bias = *(const float4*)(b0 + o);
    float bv[4] = {bias.x, bias.y, bias.z, bias.w};
#pragma unroll
    for (int i = 0; i < 8; ++i)
#pragma unroll
        for (int j = 0; j < 4; ++j) acc[i][j] += bv[j];

#pragma unroll
    for (int j = 0; j < 4; ++j) {
        float* dst = g_bufA + (size_t)(o+j)*PP + pbase + pp;
        float4 u0 = {acc[0][j], acc[1][j], acc[2][j], acc[3][j]};
        float4 u1 = {acc[4][j], acc[5][j], acc[6][j], acc[7][j]};
        ((float4*)dst)[0] = u0; ((float4*)dst)[1] = u1;
    }
    float sj[4] = {0,0,0,0}, qj[4] = {0,0,0,0};
#pragma unroll
    for (int i = 0; i < 8; ++i)
#pragma unroll
        for (int j = 0; j < 4; ++j) { sj[j] += acc[i][j]; qj[j] += acc[i][j]*acc[i][j]; }
    __syncthreads();
    float* red = Xs;   // overlay: [2][16][64]
    {
        float4 a = {sj[0], sj[1], sj[2], sj[3]};
        float4 b2 = {qj[0], qj[1], qj[2], qj[3]};
        *(float4*)(red + pgg*64 + o) = a;
        *(float4*)(red + 1024 + pgg*64 + o) = b2;
    }
    __syncthreads();
    if (tid < 64) {
        float S = 0.f, Q = 0.f;
#pragma unroll
        for (int g = 0; g < 16; ++g) { S += red[g*64 + tid]; Q += red[1024 + g*64 + tid]; }
        atomicAdd(&g_stat1[tid], S);
        atomicAdd(&g_stat1[64 + tid], Q);
    }
}

// ---------------- conv2: BN1 coeff in-block, batched X loads, GEMM(64->64) f32x2 ----------------
__global__ __launch_bounds__(256)
void conv2_kernel(const float* __restrict__ w1, const float* __restrict__ b1,
                  const float* __restrict__ g0, const float* __restrict__ bt0) {
    extern __shared__ float sm[];
    float* Ws = sm;                 // [64][64]
    float* Xs = sm + 64*64;         // [64][128]
    float* sc1 = Xs + 64*128;       // [64]
    float* sh1 = sc1 + 64;          // [64]
    int tid = threadIdx.x, lane = tid & 31, w = tid >> 5;
    int pbase = blockIdx.x * 128;

    // batched DRAM loads first (MLP=8)
    float4 v[8];
#pragma unroll
    for (int i = 0; i < 8; ++i)
        v[i] = *(const float4*)(g_bufA + (size_t)(w + i*8)*PP + pbase + lane*4);

    if (tid < 64) {
        float sc, sh;
        bn_coeff(g_stat1, O1, tid, g0, bt0, sc, sh);
        sc1[tid] = sc; sh1[tid] = sh;
    }
    {
        int o = tid & 63, cq = tid >> 6;
#pragma unroll
        for (int k = 0; k < 16; ++k) {
            int c = cq*16 + k;
            Ws[c*64 + o] = w1[o*64 + c];
        }
    }
    __syncthreads();
#pragma unroll
    for (int i = 0; i < 8; ++i) {
        int c = w + i*8;
        float sc = sc1[c], sh = sh1[c];
        float4 u = v[i];
        u.x = fmaxf(fmaf(u.x, sc, sh), 0.f);
        u.y = fmaxf(fmaf(u.y, sc, sh), 0.f);
        u.z = fmaxf(fmaf(u.z, sc, sh), 0.f);
        u.w = fmaxf(fmaf(u.w, sc, sh), 0.f);
        *(float4*)(Xs + c*128 + lane*4) = u;
    }
    __syncthreads();

    int og = tid & 15, o = og*4;
    int pgg = tid >> 4, pp = pgg*8;
    ull_t accp[4][4];
#pragma unroll
    for (int i = 0; i < 4; ++i)
#pragma unroll
        for (int j = 0; j < 4; ++j) accp[i][j] = 0ull;
#pragma unroll 4
    for (int c = 0; c < 64; ++c) {
        ulonglong2 xa = *(const ulonglong2*)(Xs + c*128 + pp);
        ulonglong2 xb2 = *(const ulonglong2*)(Xs + c*128 + pp + 4);
        float4 wv = *(const float4*)(Ws + c*64 + o);
        ull_t xs[4] = {xa.x, xa.y, xb2.x, xb2.y};
        ull_t ws[4] = {dup2(wv.x), dup2(wv.y), dup2(wv.z), dup2(wv.w)};
#pragma unroll
        for (int i = 0; i < 4; ++i)
#pragma unroll
            for (int j = 0; j < 4; ++j)
                FMA2(accp[i][j], xs[i], ws[j], accp[i][j]);
    }
    float acc[8][4];
#pragma unroll
    for (int i = 0; i < 4; ++i)
#pragma unroll
        for (int j = 0; j < 4; ++j) {
            acc[2*i][j] = ull_lo(accp[i][j]);
            acc[2*i+1][j] = ull_hi(accp[i][j]);
        }
    float4 bias = *(const float4*)(b1 + o);
    float bv[4] = {bias.x, bias.y, bias.z, bias.w};
#pragma unroll
    for (int i = 0; i < 8; ++i)
#pragma unroll
        for (int j = 0; j < 4; ++j) acc[i][j] += bv[j];
#pragma unroll
    for (int j = 0; j < 4; ++j) {
        float* dst = g_bufB + (size_t)(o+j)*PP + pbase + pp;
        float4 u0 = {acc[0][j], acc[1][j], acc[2][j], acc[3][j]};
        float4 u1 = {acc[4][j], acc[5][j], acc[6][j], acc[7][j]};
        ((float4*)dst)[0] = u0; ((float4*)dst)[1] = u1;
    }
    float sj[4] = {0,0,0,0}, qj[4] = {0,0,0,0};
#pragma unroll
    for (int i = 0; i < 8; ++i)
#pragma unroll
        for (int j = 0; j < 4; ++j) { sj[j] += acc[i][j]; qj[j] += acc[i][j]*acc[i][j]; }
    __syncthreads();
    float* red = Xs;
    {
        float4 a = {sj[0], sj[1], sj[2], sj[3]};
        float4 b2 = {qj[0], qj[1], qj[2], qj[3]};
        *(float4*)(red + pgg*64 + o) = a;
        *(float4*)(red + 1024 + pgg*64 + o) = b2;
    }
    __syncthreads();
    if (tid < 64) {
        float S = 0.f, Q = 0.f;
#pragma unroll
        for (int g = 0; g < 16; ++g) { S += red[g*64 + tid]; Q += red[1024 + g*64 + tid]; }
        atomicAdd(&g_stat2[tid], S);
        atomicAdd(&g_stat2[64 + tid], Q);
    }
}

// ---------------- conv3: BN2 coeff in-block, batched X loads, GEMM(64->128) f32x2, fused max/min ----------------
__global__ __launch_bounds__(256)
void conv3_kernel(const float* __restrict__ w2, const float* __restrict__ b2p,
                  const float* __restrict__ g1, const float* __restrict__ bt1) {
    extern __shared__ float sm[];
    float* Ws = sm;                 // [64][128]
    float* Xs = sm + 64*128;        // [64][128]
    float* sc2 = Xs + 64*128;       // [64]
    float* sh2 = sc2 + 64;          // [64]
    int tid = threadIdx.x, lane = tid & 31, w = tid >> 5;
    int pbase = blockIdx.x * 128;

    // batched DRAM loads first (MLP=8)
    float4 v[8];
#pragma unroll
    for (int i = 0; i < 8; ++i)
        v[i] = *(const float4*)(g_bufB + (size_t)(w + i*8)*PP + pbase + lane*4);

    if (tid < 64) {
        float sc, sh;
        bn_coeff(g_stat2, O2, tid, g1, bt1, sc, sh);
        sc2[tid] = sc; sh2[tid] = sh;
    }
    {
        int o = tid & 127, ch = tid >> 7;
#pragma unroll
        for (int cc = 0; cc < 32; ++cc) {
            int c = ch*32 + cc;
            Ws[c*128 + o] = w2[o*64 + c];
        }
    }
    __syncthreads();
#pragma unroll
    for (int i = 0; i < 8; ++i) {
        int c = w + i*8;
        float sc = sc2[c], sh = sh2[c];
        float4 u = v[i];
        u.x = fmaxf(fmaf(u.x, sc, sh), 0.f);
        u.y = fmaxf(fmaf(u.y, sc, sh), 0.f);
        u.z = fmaxf(fmaf(u.z, sc, sh), 0.f);
        u.w = fmaxf(fmaf(u.w, sc, sh), 0.f);
        *(float4*)(Xs + c*128 + lane*4) = u;
    }
    __syncthreads();

    int og = tid & 15, o = og*8;
    int pgg = tid >> 4, pp = pgg*8;
    ull_t accp[4][8];
#pragma unroll
    for (int i = 0; i < 4; ++i)
#pragma unroll
        for (int j = 0; j < 8; ++j) accp[i][j] = 0ull;
#pragma unroll 2
    for (int c = 0; c < 64; ++c) {
        ulonglong2 xa = *(const ulonglong2*)(Xs + c*128 + pp);
        ulonglong2 xb2 = *(const ulonglong2*)(Xs + c*128 + pp + 4);
        float4 wa = *(const float4*)(Ws + c*128 + o);
        float4 wb = *(const float4*)(Ws + c*128 + o + 4);
        ull_t xs[4] = {xa.x, xa.y, xb2.x, xb2.y};
        ull_t ws[8] = {dup2(wa.x), dup2(wa.y), dup2(wa.z), dup2(wa.w),
                       dup2(wb.x), dup2(wb.y), dup2(wb.z), dup2(wb.w)};
#pragma unroll
        for (int i = 0; i < 4; ++i)
#pragma unroll
            for (int j = 0; j < 8; ++j)
                FMA2(accp[i][j], xs[i], ws[j], accp[i][j]);
    }
    float acc[8][8];
#pragma unroll
    for (int i = 0; i < 4; ++i)
#pragma unroll
        for (int j = 0; j < 8; ++j) {
            acc[2*i][j] = ull_lo(accp[i][j]);
            acc[2*i+1][j] = ull_hi(accp[i][j]);
        }
    float4 ba = *(const float4*)(b2p + o);
    float4 bbv = *(const float4*)(b2p + o + 4);
    float bv[8] = {ba.x, ba.y, ba.z, ba.w, bbv.x, bbv.y, bbv.z, bbv.w};
#pragma unroll
    for (int i = 0; i < 8; ++i)
#pragma unroll
        for (int j = 0; j < 8; ++j) acc[i][j] += bv[j];

    float sj[8], qj[8], mxv[8], mnv[8];
#pragma unroll
    for (int j = 0; j < 8; ++j) {
        sj[j] = acc[0][j]; qj[j] = acc[0][j]*acc[0][j];
        mxv[j] = acc[0][j]; mnv[j] = acc[0][j];
    }
#pragma unroll
    for (int i = 1; i < 8; ++i)
#pragma unroll
        for (int j = 0; j < 8; ++j) {
            sj[j] += acc[i][j]; qj[j] += acc[i][j]*acc[i][j];
            mxv[j] = fmaxf(mxv[j], acc[i][j]);
            mnv[j] = fminf(mnv[j], acc[i][j]);
        }
    __syncthreads();
    float* red = Xs;   // overlay: [4][16][128] = S, Q, MX, MN (32 KB)
    {
        float4 a0 = {sj[0], sj[1], sj[2], sj[3]};
        float4 a1 = {sj[4], sj[5], sj[6], sj[7]};
        float4 q0 = {qj[0], qj[1], qj[2], qj[3]};
        float4 q1 = {qj[4], qj[5], qj[6], qj[7]};
        float4 m0 = {mxv[0], mxv[1], mxv[2], mxv[3]};
        float4 m1 = {mxv[4], mxv[5], mxv[6], mxv[7]};
        float4 n0 = {mnv[0], mnv[1], mnv[2], mnv[3]};
        float4 n1 = {mnv[4], mnv[5], mnv[6], mnv[7]};
        *(float4*)(red + pgg*128 + o) = a0;
        *(float4*)(red + pgg*128 + o + 4) = a1;
        *(float4*)(red + 2048 + pgg*128 + o) = q0;
        *(float4*)(red + 2048 + pgg*128 + o + 4) = q1;
        *(float4*)(red + 4096 + pgg*128 + o) = m0;
        *(float4*)(red + 4096 + pgg*128 + o + 4) = m1;
        *(float4*)(red + 6144 + pgg*128 + o) = n0;
        *(float4*)(red + 6144 + pgg*128 + o + 4) = n1;
    }
    __syncthreads();
    if (tid < 128) {
        float S = 0.f, Q = 0.f;
#pragma unroll
        for (int g = 0; g < 16; ++g) { S += red[g*128 + tid]; Q += red[2048 + g*128 + tid]; }
        atomicAdd(&g_stat3[tid], S);
        atomicAdd(&g_stat3[128 + tid], Q);
    }
#pragma unroll
    for (int t = tid; t < 512; t += 256) {
        int g4 = t >> 7, o2 = t & 127;
        float m = red[4096 + (g4*4)*128 + o2];
        float n2 = red[6144 + (g4*4)*128 + o2];
#pragma unroll
        for (int k = 1; k < 4; ++k) {
            m = fmaxf(m, red[4096 + (g4*4+k)*128 + o2]);
            n2 = fminf(n2, red[6144 + (g4*4+k)*128 + o2]);
        }
        g_max3[(size_t)o2*BSS + blockIdx.x*4 + g4] = m;
        g_min3[(size_t)o2*BSS + blockIdx.x*4 + g4] = n2;
    }
}

// ---------------- final: BN3 coeff per-thread + affine on max/min + ReLU ----------------
__global__ void final_kernel(float* __restrict__ out,
                             const float* __restrict__ g2,
                             const float* __restrict__ bt2) {
    int idx = blockIdx.x * 256 + threadIdx.x;
    int b = idx >> 16;
    int rem = idx & 65535;
    int o = rem >> 9;
    int s = rem & 511;
    float sc, sh;
    bn_coeff(g_stat3, O3, o, g2, bt2, sc, sh);
    float mx = g_max3[(size_t)o*BSS + b*512 + s];
    float mn = g_min3[(size_t)o*BSS + b*512 + s];
    float y = (sc >= 0.f) ? fmaf(sc, mx, sh) : fmaf(sc, mn, sh);
    out[BB*3*SS + idx] = fmaxf(y, 0.f);
}

// ---------------- launch ----------------
extern "C" void kernel_launch(void* const* d_in, const int* in_sizes, int n_in,
                              void* d_out, int out_size) {
    (void)in_sizes; (void)n_in; (void)out_size;
    const float* xyz = (const float*)d_in[0];
    const float* pts = (const float*)d_in[1];
    const float* w0  = (const float*)d_in[2];
    const float* b0  = (const float*)d_in[3];
    const float* g0  = (const float*)d_in[4];
    const float* bt0 = (const float*)d_in[5];
    const float* w1  = (const float*)d_in[6];
    const float* b1  = (const float*)d_in[7];
    const float* g1  = (const float*)d_in[8];
    const float* bt1 = (const float*)d_in[9];
    const float* w2  = (const float*)d_in[10];
    const float* b2  = (const float*)d_in[11];
    const float* g2  = (const float*)d_in[12];
    const float* bt2 = (const float*)d_in[13];
    float* out = (float*)d_out;

    const int smem1 = (C0P*O1 + C0P*128)*4;
    const int smem2 = (64*64 + 64*128 + 128)*4;
    const int smem3 = (64*128 + 64*128 + 128)*4;
    cudaFuncSetAttribute(conv1_kernel, cudaFuncAttributeMaxDynamicSharedMemorySize, smem1);
    cudaFuncSetAttribute(conv2_kernel, cudaFuncAttributeMaxDynamicSharedMemorySize, smem2);
    cudaFuncSetAttribute(conv3_kernel, cudaFuncAttributeMaxDynamicSharedMemorySize, smem3);

    build_feat_kernel<<<BB*NN/256, 256>>>(xyz, pts);
    fps_kernel<<<BB, 256>>>(xyz, out);
    ball_kernel<<<BB*64, 256>>>(xyz, out);
    conv1_kernel<<<PP/128, 256, smem1>>>(w0, b0, out);
    conv2_kernel<<<PP/128, 256, smem2>>>(w1, b1, g0, bt0);
    conv3_kernel<<<PP/128, 256, smem3>>>(w2, b2, g1, bt1);
    final_kernel<<<BB*O3*SS/256, 256>>>(out, g2, bt2);
}

// round 8
// speedup vs baseline: 1.1586x; 1.0603x over previous
#include <cuda_runtime.h>
#include <math.h>

// Problem constants
#define BB 16
#define NN 2048
#define SS 512      // npoint
#define KK 32       // nsample
#define PP (BB*SS*KK)   // 262144 total "points" through the MLP
#define BSS (BB*SS)
#define C0 67
#define U1W 68      // u1 row stride: 64 feature outs + xyz + pad
#define O1 64
#define O2 64
#define O3 128

typedef unsigned long long ull_t;

#define FMA2(d, a, b, c) \
    asm("fma.rn.f32x2 %0, %1, %2, %3;" : "=l"(d) : "l"(a), "l"(b), "l"(c))

__device__ __forceinline__ float ull_lo(ull_t v) {
    return __uint_as_float((unsigned)(v & 0xffffffffull));
}
__device__ __forceinline__ float ull_hi(ull_t v) {
    return __uint_as_float((unsigned)(v >> 32));
}
__device__ __forceinline__ ull_t dup2(float v) {
    unsigned u = __float_as_uint(v);
    ull_t r;
    asm("mov.b64 %0, {%1, %1};" : "=l"(r) : "r"(u));
    return r;
}
__device__ __forceinline__ ull_t packf(float lo, float hi) {
    ull_t r;
    asm("mov.b64 %0, {%1, %2};" : "=l"(r) : "f"(lo), "f"(hi));
    return r;
}

// ---------------- scratch ----------------
static __device__ __align__(16) float g_u1[(size_t)BB*NN*U1W];    // 8.9 MB [n][68]: 64 outs + xyz
static __device__ int   g_bidx[PP];                               // ball-query indices
static __device__ __align__(16) float g_bufA[(size_t)O1*PP];      // 67 MB   (conv1 out)
static __device__ __align__(16) float g_bufB[(size_t)O2*PP];      // 67 MB   (conv2 out)
static __device__ __align__(16) float g_max3[(size_t)O3*BSS];     // 4 MB
static __device__ __align__(16) float g_min3[(size_t)O3*BSS];     // 4 MB
static __device__ float g_stat1[2*O1], g_stat2[2*O2], g_stat3[2*O3];

__device__ __forceinline__ void bn_coeff(const float* stat, int C, int o,
                                         const float* g, const float* bt,
                                         float& sc, float& sh) {
    const float invN = 1.f / (float)PP;
    float mean = stat[o] * invN;
    float var = fmaxf(stat[C + o] * invN - mean*mean, 0.f);
    float is = rsqrtf(var + 1e-5f);
    float s = g[o] * is;
    sc = s;
    sh = fmaf(-mean, s, bt[o]);
}

// ---------------- u1: dense GEMM over unique points (64 pt-channels -> 64), + xyz copy ----------------
__global__ __launch_bounds__(256)
void u1_kernel(const float* __restrict__ pts, const float* __restrict__ w0,
               const float* __restrict__ b0, const float* __restrict__ xyz) {
    extern __shared__ float sm[];
    float* Ws = sm;            // [64][64]
    float* Xs = sm + 64*64;    // [64][128]
    int tid = threadIdx.x, lane = tid & 31, w = tid >> 5;
    if (blockIdx.x == 0) {
        if (tid < 2*O1) g_stat1[tid] = 0.f;
        if (tid < 2*O2) g_stat2[tid] = 0.f;
        if (tid < 2*O3) g_stat3[tid] = 0.f;
    }
    int b = blockIdx.x >> 4;
    int n0 = (blockIdx.x & 15) * 128;
    const float* src = pts + (size_t)b*64*NN;
    float4 v[8];
#pragma unroll
    for (int i = 0; i < 8; ++i) {
        int c = w + i*8;
        v[i] = *(const float4*)(src + c*NN + n0 + lane*4);
    }
    {
        int o = tid & 63, cq = tid >> 6;
#pragma unroll
        for (int k = 0; k < 16; ++k) {
            int c = cq*16 + k;
            Ws[c*64 + o] = w0[o*C0 + 3 + c];
        }
    }
#pragma unroll
    for (int i = 0; i < 8; ++i) {
        int c = w + i*8;
        *(float4*)(Xs + c*128 + lane*4) = v[i];
    }
    __syncthreads();

    int og = tid & 15, o = og*4;
    int pgg = tid >> 4, pp = pgg*8;
    ull_t accp[4][4];
#pragma unroll
    for (int i = 0; i < 4; ++i)
#pragma unroll
        for (int j = 0; j < 4; ++j) accp[i][j] = 0ull;
#pragma unroll 4
    for (int c = 0; c < 64; ++c) {
        ulonglong2 xa = *(const ulonglong2*)(Xs + c*128 + pp);
        ulonglong2 xb2 = *(const ulonglong2*)(Xs + c*128 + pp + 4);
        float4 wv = *(const float4*)(Ws + c*64 + o);
        ull_t xs[4] = {xa.x, xa.y, xb2.x, xb2.y};
        ull_t ws[4] = {dup2(wv.x), dup2(wv.y), dup2(wv.z), dup2(wv.w)};
#pragma unroll
        for (int i = 0; i < 4; ++i)
#pragma unroll
            for (int j = 0; j < 4; ++j)
                FMA2(accp[i][j], xs[i], ws[j], accp[i][j]);
    }
    float acc[8][4];
#pragma unroll
    for (int i = 0; i < 4; ++i)
#pragma unroll
        for (int j = 0; j < 4; ++j) {
            acc[2*i][j] = ull_lo(accp[i][j]);
            acc[2*i+1][j] = ull_hi(accp[i][j]);
        }
    float4 bias = *(const float4*)(b0 + o);
    float bv[4] = {bias.x, bias.y, bias.z, bias.w};
#pragma unroll
    for (int i = 0; i < 8; ++i)
#pragma unroll
        for (int j = 0; j < 4; ++j) acc[i][j] += bv[j];
#pragma unroll
    for (int i = 0; i < 8; ++i) {
        size_t r = (size_t)b*NN + n0 + pp + i;
        float4 uo = {acc[i][0], acc[i][1], acc[i][2], acc[i][3]};
        *(float4*)(g_u1 + r*U1W + o) = uo;
    }
    if (og == 0) {
#pragma unroll
        for (int i = 0; i < 8; ++i) {
            int n = n0 + pp + i;
            size_t r = (size_t)b*NN + n;
            g_u1[r*U1W + 64] = xyz[b*3*NN + n];
            g_u1[r*U1W + 65] = xyz[b*3*NN + NN + n];
            g_u1[r*U1W + 66] = xyz[b*3*NN + 2*NN + n];
            g_u1[r*U1W + 67] = 0.f;
        }
    }
}

// ---------------- FPS: one block/batch, 256 thr x 8 pts, REDUX argmax ----------------
__global__ __launch_bounds__(256)
void fps_kernel(const float* __restrict__ xyz, float* __restrict__ out) {
    __shared__ float sx[NN], sy[NN], sz[NN];
    __shared__ unsigned swb[2][8], swi[2][8];
    int b = blockIdx.x;
    const float* xb = xyz + b * 3 * NN;
    int tid = threadIdx.x, lane = tid & 31, wid = tid >> 5;
    for (int i = tid; i < NN; i += 256) {
        sx[i] = xb[i]; sy[i] = xb[NN + i]; sz[i] = xb[2*NN + i];
    }
    __syncthreads();
    float px[8], py[8], pz[8], dist[8];
#pragma unroll
    for (int i = 0; i < 8; ++i) {
        int n = tid + i*256;
        px[i] = sx[n]; py[i] = sy[n]; pz[i] = sz[n];
        dist[i] = 1e10f;
    }
    int far = 0, pb = 0;
    float* ob = out + b * 3 * SS;
    for (int it = 0; it < SS; ++it) {
        float cx = sx[far], cy = sy[far], cz = sz[far];
        if (tid == 0) { ob[it] = cx; ob[SS+it] = cy; ob[2*SS+it] = cz; }
        unsigned bb = 0u; unsigned bi = 0xffffffffu;
#pragma unroll
        for (int i = 0; i < 8; ++i) {
            float dx = px[i]-cx, dy = py[i]-cy, dz = pz[i]-cz;
            float d = dx*dx; d += dy*dy; d += dz*dz;
            float dd = fminf(dist[i], d); dist[i] = dd;
            unsigned bits = __float_as_uint(dd);   // monotone for dd >= 0
            if (bits > bb) { bb = bits; bi = (unsigned)(tid + i*256); }
        }
        unsigned wm = __reduce_max_sync(0xffffffffu, bb);
        unsigned cand = (bb == wm) ? bi : 0xffffffffu;
        unsigned wi = __reduce_min_sync(0xffffffffu, cand);   // first-index tie-break
        if (lane == 0) { swb[pb][wid] = wm; swi[pb][wid] = wi; }
        __syncthreads();
        unsigned b2 = swb[pb][lane & 7];
        unsigned i2 = swi[pb][lane & 7];
        unsigned m2 = __reduce_max_sync(0xffffffffu, b2);
        unsigned c2 = (b2 == m2) ? i2 : 0xffffffffu;
        far = (int)__reduce_min_sync(0xffffffffu, c2);
        pb ^= 1;
    }
}

// ---------------- ball query: smem-staged xyz; warp per center ----------------
__global__ __launch_bounds__(256)
void ball_kernel(const float* __restrict__ xyz,
                 const float* __restrict__ newxyz /* = d_out head */) {
    __shared__ float sx[NN], sy[NN], sz[NN];
    int b = blockIdx.x >> 6, schunk = blockIdx.x & 63;
    const float* xb = xyz + b * 3 * NN;
    for (int i = threadIdx.x; i < NN; i += 256) {
        sx[i] = xb[i]; sy[i] = xb[NN + i]; sz[i] = xb[2*NN + i];
    }
    __syncthreads();
    int w = threadIdx.x >> 5, lane = threadIdx.x & 31;
    int s = schunk * 8 + w;
    float cx = newxyz[b*3*SS + s];
    float cy = newxyz[b*3*SS + SS + s];
    float cz = newxyz[b*3*SS + 2*SS + s];
    int* dst = g_bidx + (b*SS + s) * KK;
    const float R2 = 0.04f;
    int count = 0, first = -1;
    for (int r = 0; r < NN/32; ++r) {
        int n = r*32 + lane;
        float dx = cx - sx[n], dy = cy - sy[n], dz = cz - sz[n];
        float d = dx*dx; d += dy*dy; d += dz*dz;
        bool q = (d <= R2);
        unsigned m = __ballot_sync(0xffffffffu, q);
        if (first < 0 && m) first = r*32 + __ffs(m) - 1;
        int pos = count + __popc(m & ((1u << lane) - 1u));
        if (q && pos < KK) dst[pos] = n;
        count += __popc(m);
        if (count >= KK) break;
    }
    if (count < KK && lane >= count && lane < KK) dst[lane] = first;
}

// ---------------- conv1': gather u1 + xyz-correction + write y1 + BN stats ----------------
__global__ __launch_bounds__(256)
void conv1p_kernel(const float* __restrict__ w0, const float* __restrict__ newxyz) {
    __shared__ __align__(16) float Wc[3*64];       // Wc[c][o]
    __shared__ __align__(16) float red[2*16*64];   // stats overlay
    int tid = threadIdx.x;
    int og = tid & 15, o = og*4;
    int pgg = tid >> 4, pp = pgg*8;
    int pbase = blockIdx.x * 128;

    if (tid < 192) Wc[tid] = w0[(tid & 63)*C0 + (tid >> 6)];

    int gp0 = pbase + pp;
    int sg = gp0 >> 5;
    int b = sg >> 9, s = sg & 511;

    int4 ia = *(const int4*)(g_bidx + gp0);
    int4 ib = *(const int4*)(g_bidx + gp0 + 4);
    int nn[8] = {ia.x, ia.y, ia.z, ia.w, ib.x, ib.y, ib.z, ib.w};

    float4 u[8], xz[8];
#pragma unroll
    for (int i = 0; i < 8; ++i) {
        size_t base = ((size_t)(b*NN + nn[i])) * U1W;
        u[i]  = *(const float4*)(g_u1 + base + o);
        xz[i] = *(const float4*)(g_u1 + base + 64);
    }
    float cx = newxyz[b*3*SS + s];
    float cy = newxyz[b*3*SS + SS + s];
    float cz = newxyz[b*3*SS + 2*SS + s];
    __syncthreads();   // Wc ready

    float4 wc0 = *(const float4*)(Wc + o);
    float4 wc1 = *(const float4*)(Wc + 64 + o);
    float4 wc2 = *(const float4*)(Wc + 128 + o);
    ull_t wx[4] = {dup2(wc0.x), dup2(wc0.y), dup2(wc0.z), dup2(wc0.w)};
    ull_t wy[4] = {dup2(wc1.x), dup2(wc1.y), dup2(wc1.z), dup2(wc1.w)};
    ull_t wz[4] = {dup2(wc2.x), dup2(wc2.y), dup2(wc2.z), dup2(wc2.w)};

    float acc[8][4];
#pragma unroll
    for (int i2 = 0; i2 < 4; ++i2) {
        int p0 = 2*i2, p1 = 2*i2 + 1;
        ull_t dx2 = packf(xz[p0].x - cx, xz[p1].x - cx);
        ull_t dy2 = packf(xz[p0].y - cy, xz[p1].y - cy);
        ull_t dz2 = packf(xz[p0].z - cz, xz[p1].z - cz);
        float u0[4] = {u[p0].x, u[p0].y, u[p0].z, u[p0].w};
        float u1v[4] = {u[p1].x, u[p1].y, u[p1].z, u[p1].w};
#pragma unroll
        for (int j = 0; j < 4; ++j) {
            ull_t a = packf(u0[j], u1v[j]);
            FMA2(a, wx[j], dx2, a);
            FMA2(a, wy[j], dy2, a);
            FMA2(a, wz[j], dz2, a);
            acc[p0][j] = ull_lo(a);
            acc[p1][j] = ull_hi(a);
        }
    }

    // write y1 (channel-major) — no bias here (bias already in u1)
#pragma unroll
    for (int j = 0; j < 4; ++j) {
        float* dst = g_bufA + (size_t)(o+j)*PP + pbase + pp;
        float4 u0 = {acc[0][j], acc[1][j], acc[2][j], acc[3][j]};
        float4 u1v = {acc[4][j], acc[5][j], acc[6][j], acc[7][j]};
        ((float4*)dst)[0] = u0; ((float4*)dst)[1] = u1v;
    }
    float sj[4] = {0,0,0,0}, qj[4] = {0,0,0,0};
#pragma unroll
    for (int i = 0; i < 8; ++i)
#pragma unroll
        for (int j = 0; j < 4; ++j) { sj[j] += acc[i][j]; qj[j] += acc[i][j]*acc[i][j]; }
    {
        float4 a = {sj[0], sj[1], sj[2], sj[3]};
        float4 b2 = {qj[0], qj[1], qj[2], qj[3]};
        *(float4*)(red + pgg*64 + o) = a;
        *(float4*)(red + 1024 + pgg*64 + o) = b2;
    }
    __syncthreads();
    if (tid < 64) {
        float S = 0.f, Q = 0.f;
#pragma unroll
        for (int g = 0; g < 16; ++g) { S += red[g*64 + tid]; Q += red[1024 + g*64 + tid]; }
        atomicAdd(&g_stat1[tid], S);
        atomicAdd(&g_stat1[64 + tid], Q);
    }
}

// ---------------- conv2: BN1 coeff in-block, batched X loads, GEMM(64->64) f32x2 ----------------
__global__ __launch_bounds__(256)
void conv2_kernel(const float* __restrict__ w1, const float* __restrict__ b1,
                  const float* __restrict__ g0, const float* __restrict__ bt0) {
    extern __shared__ float sm[];
    float* Ws = sm;                 // [64][64]
    float* Xs = sm + 64*64;         // [64][128]
    float* sc1 = Xs + 64*128;       // [64]
    float* sh1 = sc1 + 64;          // [64]
    int tid = threadIdx.x, lane = tid & 31, w = tid >> 5;
    int pbase = blockIdx.x * 128;

    float4 v[8];
#pragma unroll
    for (int i = 0; i < 8; ++i)
        v[i] = *(const float4*)(g_bufA + (size_t)(w + i*8)*PP + pbase + lane*4);

    if (tid < 64) {
        float sc, sh;
        bn_coeff(g_stat1, O1, tid, g0, bt0, sc, sh);
        sc1[tid] = sc; sh1[tid] = sh;
    }
    {
        int o = tid & 63, cq = tid >> 6;
#pragma unroll
        for (int k = 0; k < 16; ++k) {
            int c = cq*16 + k;
            Ws[c*64 + o] = w1[o*64 + c];
        }
    }
    __syncthreads();
#pragma unroll
    for (int i = 0; i < 8; ++i) {
        int c = w + i*8;
        float sc = sc1[c], sh = sh1[c];
        float4 u = v[i];
        u.x = fmaxf(fmaf(u.x, sc, sh), 0.f);
        u.y = fmaxf(fmaf(u.y, sc, sh), 0.f);
        u.z = fmaxf(fmaf(u.z, sc, sh), 0.f);
        u.w = fmaxf(fmaf(u.w, sc, sh), 0.f);
        *(float4*)(Xs + c*128 + lane*4) = u;
    }
    __syncthreads();

    int og = tid & 15, o = og*4;
    int pgg = tid >> 4, pp = pgg*8;
    ull_t accp[4][4];
#pragma unroll
    for (int i = 0; i < 4; ++i)
#pragma unroll
        for (int j = 0; j < 4; ++j) accp[i][j] = 0ull;
#pragma unroll 4
    for (int c = 0; c < 64; ++c) {
        ulonglong2 xa = *(const ulonglong2*)(Xs + c*128 + pp);
        ulonglong2 xb2 = *(const ulonglong2*)(Xs + c*128 + pp + 4);
        float4 wv = *(const float4*)(Ws + c*64 + o);
        ull_t xs[4] = {xa.x, xa.y, xb2.x, xb2.y};
        ull_t ws[4] = {dup2(wv.x), dup2(wv.y), dup2(wv.z), dup2(wv.w)};
#pragma unroll
        for (int i = 0; i < 4; ++i)
#pragma unroll
            for (int j = 0; j < 4; ++j)
                FMA2(accp[i][j], xs[i], ws[j], accp[i][j]);
    }
    float acc[8][4];
#pragma unroll
    for (int i = 0; i < 4; ++i)
#pragma unroll
        for (int j = 0; j < 4; ++j) {
            acc[2*i][j] = ull_lo(accp[i][j]);
            acc[2*i+1][j] = ull_hi(accp[i][j]);
        }
    float4 bias = *(const float4*)(b1 + o);
    float bv[4] = {bias.x, bias.y, bias.z, bias.w};
#pragma unroll
    for (int i = 0; i < 8; ++i)
#pragma unroll
        for (int j = 0; j < 4; ++j) acc[i][j] += bv[j];
#pragma unroll
    for (int j = 0; j < 4; ++j) {
        float* dst = g_bufB + (size_t)(o+j)*PP + pbase + pp;
        float4 u0 = {acc[0][j], acc[1][j], acc[2][j], acc[3][j]};
        float4 u1v = {acc[4][j], acc[5][j], acc[6][j], acc[7][j]};
        ((float4*)dst)[0] = u0; ((float4*)dst)[1] = u1v;
    }
    float sj[4] = {0,0,0,0}, qj[4] = {0,0,0,0};
#pragma unroll
    for (int i = 0; i < 8; ++i)
#pragma unroll
        for (int j = 0; j < 4; ++j) { sj[j] += acc[i][j]; qj[j] += acc[i][j]*acc[i][j]; }
    __syncthreads();
    float* red = Xs;
    {
        float4 a = {sj[0], sj[1], sj[2], sj[3]};
        float4 b2 = {qj[0], qj[1], qj[2], qj[3]};
        *(float4*)(red + pgg*64 + o) = a;
        *(float4*)(red + 1024 + pgg*64 + o) = b2;
    }
    __syncthreads();
    if (tid < 64) {
        float S = 0.f, Q = 0.f;
#pragma unroll
        for (int g = 0; g < 16; ++g) { S += red[g*64 + tid]; Q += red[1024 + g*64 + tid]; }
        atomicAdd(&g_stat2[tid], S);
        atomicAdd(&g_stat2[64 + tid], Q);
    }
}

// ---------------- conv3: BN2 coeff in-block, batched X loads, GEMM(64->128) f32x2, fused max/min ----------------
__global__ __launch_bounds__(256)
void conv3_kernel(const float* __restrict__ w2, const float* __restrict__ b2p,
                  const float* __restrict__ g1, const float* __restrict__ bt1) {
    extern __shared__ float sm[];
    float* Ws = sm;                 // [64][128]
    float* Xs = sm + 64*128;        // [64][128]
    float* sc2 = Xs + 64*128;       // [64]
    float* sh2 = sc2 + 64;          // [64]
    int tid = threadIdx.x, lane = tid & 31, w = tid >> 5;
    int pbase = blockIdx.x * 128;

    float4 v[8];
#pragma unroll
    for (int i = 0; i < 8; ++i)
        v[i] = *(const float4*)(g_bufB + (size_t)(w + i*8)*PP + pbase + lane*4);

    if (tid < 64) {
        float sc, sh;
        bn_coeff(g_stat2, O2, tid, g1, bt1, sc, sh);
        sc2[tid] = sc; sh2[tid] = sh;
    }
    {
        int o = tid & 127, ch = tid >> 7;
#pragma unroll
        for (int cc = 0; cc < 32; ++cc) {
            int c = ch*32 + cc;
            Ws[c*128 + o] = w2[o*64 + c];
        }
    }
    __syncthreads();
#pragma unroll
    for (int i = 0; i < 8; ++i) {
        int c = w + i*8;
        float sc = sc2[c], sh = sh2[c];
        float4 u = v[i];
        u.x = fmaxf(fmaf(u.x, sc, sh), 0.f);
        u.y = fmaxf(fmaf(u.y, sc, sh), 0.f);
        u.z = fmaxf(fmaf(u.z, sc, sh), 0.f);
        u.w = fmaxf(fmaf(u.w, sc, sh), 0.f);
        *(float4*)(Xs + c*128 + lane*4) = u;
    }
    __syncthreads();

    int og = tid & 15, o = og*8;
    int pgg = tid >> 4, pp = pgg*8;
    ull_t accp[4][8];
#pragma unroll
    for (int i = 0; i < 4; ++i)
#pragma unroll
        for (int j = 0; j < 8; ++j) accp[i][j] = 0ull;
#pragma unroll 2
    for (int c = 0; c < 64; ++c) {
        ulonglong2 xa = *(const ulonglong2*)(Xs + c*128 + pp);
        ulonglong2 xb2 = *(const ulonglong2*)(Xs + c*128 + pp + 4);
        float4 wa = *(const float4*)(Ws + c*128 + o);
        float4 wb = *(const float4*)(Ws + c*128 + o + 4);
        ull_t xs[4] = {xa.x, xa.y, xb2.x, xb2.y};
        ull_t ws[8] = {dup2(wa.x), dup2(wa.y), dup2(wa.z), dup2(wa.w),
                       dup2(wb.x), dup2(wb.y), dup2(wb.z), dup2(wb.w)};
#pragma unroll
        for (int i = 0; i < 4; ++i)
#pragma unroll
            for (int j = 0; j < 8; ++j)
                FMA2(accp[i][j], xs[i], ws[j], accp[i][j]);
    }
    float acc[8][8];
#pragma unroll
    for (int i = 0; i < 4; ++i)
#pragma unroll
        for (int j = 0; j < 8; ++j) {
            acc[2*i][j] = ull_lo(accp[i][j]);
            acc[2*i+1][j] = ull_hi(accp[i][j]);
        }
    float4 ba = *(const float4*)(b2p + o);
    float4 bbv = *(const float4*)(b2p + o + 4);
    float bv[8] = {ba.x, ba.y, ba.z, ba.w, bbv.x, bbv.y, bbv.z, bbv.w};
#pragma unroll
    for (int i = 0; i < 8; ++i)
#pragma unroll
        for (int j = 0; j < 8; ++j) acc[i][j] += bv[j];

    float sj[8], qj[8], mxv[8], mnv[8];
#pragma unroll
    for (int j = 0; j < 8; ++j) {
        sj[j] = acc[0][j]; qj[j] = acc[0][j]*acc[0][j];
        mxv[j] = acc[0][j]; mnv[j] = acc[0][j];
    }
#pragma unroll
    for (int i = 1; i < 8; ++i)
#pragma unroll
        for (int j = 0; j < 8; ++j) {
            sj[j] += acc[i][j]; qj[j] += acc[i][j]*acc[i][j];
            mxv[j] = fmaxf(mxv[j], acc[i][j]);
            mnv[j] = fminf(mnv[j], acc[i][j]);
        }
    __syncthreads();
    float* red = Xs;   // overlay: [4][16][128]
    {
        float4 a0 = {sj[0], sj[1], sj[2], sj[3]};
        float4 a1 = {sj[4], sj[5], sj[6], sj[7]};
        float4 q0 = {qj[0], qj[1], qj[2], qj[3]};
        float4 q1 = {qj[4], qj[5], qj[6], qj[7]};
        float4 m0 = {mxv[0], mxv[1], mxv[2], mxv[3]};
        float4 m1 = {mxv[4], mxv[5], mxv[6], mxv[7]};
        float4 n0 = {mnv[0], mnv[1], mnv[2], mnv[3]};
        float4 n1 = {mnv[4], mnv[5], mnv[6], mnv[7]};
        *(float4*)(red + pgg*128 + o) = a0;
        *(float4*)(red + pgg*128 + o + 4) = a1;
        *(float4*)(red + 2048 + pgg*128 + o) = q0;
        *(float4*)(red + 2048 + pgg*128 + o + 4) = q1;
        *(float4*)(red + 4096 + pgg*128 + o) = m0;
        *(float4*)(red + 4096 + pgg*128 + o + 4) = m1;
        *(float4*)(red + 6144 + pgg*128 + o) = n0;
        *(float4*)(red + 6144 + pgg*128 + o + 4) = n1;
    }
    __syncthreads();
    if (tid < 128) {
        float S = 0.f, Q = 0.f;
#pragma unroll
        for (int g = 0; g < 16; ++g) { S += red[g*128 + tid]; Q += red[2048 + g*128 + tid]; }
        atomicAdd(&g_stat3[tid], S);
        atomicAdd(&g_stat3[128 + tid], Q);
    }
#pragma unroll
    for (int t = tid; t < 512; t += 256) {
        int g4 = t >> 7, o2 = t & 127;
        float m = red[4096 + (g4*4)*128 + o2];
        float n2 = red[6144 + (g4*4)*128 + o2];
#pragma unroll
        for (int k = 1; k < 4; ++k) {
            m = fmaxf(m, red[4096 + (g4*4+k)*128 + o2]);
            n2 = fminf(n2, red[6144 + (g4*4+k)*128 + o2]);
        }
        g_max3[(size_t)o2*BSS + blockIdx.x*4 + g4] = m;
        g_min3[(size_t)o2*BSS + blockIdx.x*4 + g4] = n2;
    }
}

// ---------------- final: BN3 coeff per-thread + affine on max/min + ReLU ----------------
__global__ void final_kernel(float* __restrict__ out,
                             const float* __restrict__ g2,
                             const float* __restrict__ bt2) {
    int idx = blockIdx.x * 256 + threadIdx.x;
    int b = idx >> 16;
    int rem = idx & 65535;
    int o = rem >> 9;
    int s = rem & 511;
    float sc, sh;
    bn_coeff(g_stat3, O3, o, g2, bt2, sc, sh);
    float mx = g_max3[(size_t)o*BSS + b*512 + s];
    float mn = g_min3[(size_t)o*BSS + b*512 + s];
    float y = (sc >= 0.f) ? fmaf(sc, mx, sh) : fmaf(sc, mn, sh);
    out[BB*3*SS + idx] = fmaxf(y, 0.f);
}

// ---------------- launch ----------------
extern "C" void kernel_launch(void* const* d_in, const int* in_sizes, int n_in,
                              void* d_out, int out_size) {
    (void)in_sizes; (void)n_in; (void)out_size;
    const float* xyz = (const float*)d_in[0];
    const float* pts = (const float*)d_in[1];
    const float* w0  = (const float*)d_in[2];
    const float* b0  = (const float*)d_in[3];
    const float* g0  = (const float*)d_in[4];
    const float* bt0 = (const float*)d_in[5];
    const float* w1  = (const float*)d_in[6];
    const float* b1  = (const float*)d_in[7];
    const float* g1  = (const float*)d_in[8];
    const float* bt1 = (const float*)d_in[9];
    const float* w2  = (const float*)d_in[10];
    const float* b2  = (const float*)d_in[11];
    const float* g2  = (const float*)d_in[12];
    const float* bt2 = (const float*)d_in[13];
    float* out = (float*)d_out;

    const int smemU = (64*64 + 64*128)*4;
    const int smem2 = (64*64 + 64*128 + 128)*4;
    const int smem3 = (64*128 + 64*128 + 128)*4;
    cudaFuncSetAttribute(u1_kernel,  cudaFuncAttributeMaxDynamicSharedMemorySize, smemU);
    cudaFuncSetAttribute(conv2_kernel, cudaFuncAttributeMaxDynamicSharedMemorySize, smem2);
    cudaFuncSetAttribute(conv3_kernel, cudaFuncAttributeMaxDynamicSharedMemorySize, smem3);

    u1_kernel<<<BB*16, 256, smemU>>>(pts, w0, b0, xyz);
    fps_kernel<<<BB, 256>>>(xyz, out);
    ball_kernel<<<BB*64, 256>>>(xyz, out);
    conv1p_kernel<<<PP/128, 256>>>(w0, out);
    conv2_kernel<<<PP/128, 256, smem2>>>(w1, b1, g0, bt0);
    conv3_kernel<<<PP/128, 256, smem3>>>(w2, b2, g1, bt1);
    final_kernel<<<BB*O3*SS/256, 256>>>(out, g2, bt2);
}

// round 9
// speedup vs baseline: 1.2192x; 1.0523x over previous
#include <cuda_runtime.h>
#include <math.h>

// Problem constants
#define BB 16
#define NN 2048
#define SS 512      // npoint
#define KK 32       // nsample
#define PP (BB*SS*KK)   // 262144 total "points" through the MLP
#define BSS (BB*SS)
#define C0 67
#define U1W 68      // u1 row stride: 64 feature outs + xyz + pad
#define O1 64
#define O2 64
#define O3 128

typedef unsigned long long ull_t;

#define FMA2(d, a, b, c) \
    asm("fma.rn.f32x2 %0, %1, %2, %3;" : "=l"(d) : "l"(a), "l"(b), "l"(c))

__device__ __forceinline__ float ull_lo(ull_t v) {
    return __uint_as_float((unsigned)(v & 0xffffffffull));
}
__device__ __forceinline__ float ull_hi(ull_t v) {
    return __uint_as_float((unsigned)(v >> 32));
}
__device__ __forceinline__ ull_t dup2(float v) {
    unsigned u = __float_as_uint(v);
    ull_t r;
    asm("mov.b64 %0, {%1, %1};" : "=l"(r) : "r"(u));
    return r;
}
__device__ __forceinline__ ull_t packf(float lo, float hi) {
    ull_t r;
    asm("mov.b64 %0, {%1, %2};" : "=l"(r) : "f"(lo), "f"(hi));
    return r;
}

// ---------------- scratch ----------------
static __device__ __align__(16) float g_u1[(size_t)BB*NN*U1W];    // 8.9 MB [n][68]: 64 outs + xyz
static __device__ int   g_bidx[PP];                               // ball-query indices
static __device__ __align__(16) float g_bufB[(size_t)O2*PP];      // 67 MB   (conv2 out)
static __device__ __align__(16) float g_max3[(size_t)O3*BSS];     // 4 MB
static __device__ __align__(16) float g_min3[(size_t)O3*BSS];     // 4 MB
static __device__ float g_stat1[2*O1], g_stat2[2*O2], g_stat3[2*O3];

__device__ __forceinline__ void bn_coeff(const float* stat, int C, int o,
                                         const float* g, const float* bt,
                                         float& sc, float& sh) {
    const float invN = 1.f / (float)PP;
    float mean = stat[o] * invN;
    float var = fmaxf(stat[C + o] * invN - mean*mean, 0.f);
    float is = rsqrtf(var + 1e-5f);
    float s = g[o] * is;
    sc = s;
    sh = fmaf(-mean, s, bt[o]);
}

// ---------------- u1: dense GEMM over unique points (64 pt-channels -> 64), + xyz copy ----------------
__global__ __launch_bounds__(256)
void u1_kernel(const float* __restrict__ pts, const float* __restrict__ w0,
               const float* __restrict__ b0, const float* __restrict__ xyz) {
    extern __shared__ float sm[];
    float* Ws = sm;            // [64][64]
    float* Xs = sm + 64*64;    // [64][128]
    int tid = threadIdx.x, lane = tid & 31, w = tid >> 5;
    if (blockIdx.x == 0) {
        if (tid < 2*O1) g_stat1[tid] = 0.f;
        if (tid < 2*O2) g_stat2[tid] = 0.f;
        if (tid < 2*O3) g_stat3[tid] = 0.f;
    }
    int b = blockIdx.x >> 4;
    int n0 = (blockIdx.x & 15) * 128;
    const float* src = pts + (size_t)b*64*NN;
    float4 v[8];
#pragma unroll
    for (int i = 0; i < 8; ++i) {
        int c = w + i*8;
        v[i] = *(const float4*)(src + c*NN + n0 + lane*4);
    }
    {
        int o = tid & 63, cq = tid >> 6;
#pragma unroll
        for (int k = 0; k < 16; ++k) {
            int c = cq*16 + k;
            Ws[c*64 + o] = w0[o*C0 + 3 + c];
        }
    }
#pragma unroll
    for (int i = 0; i < 8; ++i) {
        int c = w + i*8;
        *(float4*)(Xs + c*128 + lane*4) = v[i];
    }
    __syncthreads();

    int og = tid & 15, o = og*4;
    int pgg = tid >> 4, pp = pgg*8;
    ull_t accp[4][4];
#pragma unroll
    for (int i = 0; i < 4; ++i)
#pragma unroll
        for (int j = 0; j < 4; ++j) accp[i][j] = 0ull;
#pragma unroll 4
    for (int c = 0; c < 64; ++c) {
        ulonglong2 xa = *(const ulonglong2*)(Xs + c*128 + pp);
        ulonglong2 xb2 = *(const ulonglong2*)(Xs + c*128 + pp + 4);
        float4 wv = *(const float4*)(Ws + c*64 + o);
        ull_t xs[4] = {xa.x, xa.y, xb2.x, xb2.y};
        ull_t ws[4] = {dup2(wv.x), dup2(wv.y), dup2(wv.z), dup2(wv.w)};
#pragma unroll
        for (int i = 0; i < 4; ++i)
#pragma unroll
            for (int j = 0; j < 4; ++j)
                FMA2(accp[i][j], xs[i], ws[j], accp[i][j]);
    }
    float acc[8][4];
#pragma unroll
    for (int i = 0; i < 4; ++i)
#pragma unroll
        for (int j = 0; j < 4; ++j) {
            acc[2*i][j] = ull_lo(accp[i][j]);
            acc[2*i+1][j] = ull_hi(accp[i][j]);
        }
    float4 bias = *(const float4*)(b0 + o);
    float bv[4] = {bias.x, bias.y, bias.z, bias.w};
#pragma unroll
    for (int i = 0; i < 8; ++i)
#pragma unroll
        for (int j = 0; j < 4; ++j) acc[i][j] += bv[j];
#pragma unroll
    for (int i = 0; i < 8; ++i) {
        size_t r = (size_t)b*NN + n0 + pp + i;
        float4 uo = {acc[i][0], acc[i][1], acc[i][2], acc[i][3]};
        *(float4*)(g_u1 + r*U1W + o) = uo;
    }
    if (og == 0) {
#pragma unroll
        for (int i = 0; i < 8; ++i) {
            int n = n0 + pp + i;
            size_t r = (size_t)b*NN + n;
            g_u1[r*U1W + 64] = xyz[b*3*NN + n];
            g_u1[r*U1W + 65] = xyz[b*3*NN + NN + n];
            g_u1[r*U1W + 66] = xyz[b*3*NN + 2*NN + n];
            g_u1[r*U1W + 67] = 0.f;
        }
    }
}

// ---------------- FPS: one block/batch, 256 thr x 8 pts, REDUX argmax ----------------
__global__ __launch_bounds__(256)
void fps_kernel(const float* __restrict__ xyz, float* __restrict__ out) {
    __shared__ float sx[NN], sy[NN], sz[NN];
    __shared__ unsigned swb[2][8], swi[2][8];
    int b = blockIdx.x;
    const float* xb = xyz + b * 3 * NN;
    int tid = threadIdx.x, lane = tid & 31, wid = tid >> 5;
    for (int i = tid; i < NN; i += 256) {
        sx[i] = xb[i]; sy[i] = xb[NN + i]; sz[i] = xb[2*NN + i];
    }
    __syncthreads();
    float px[8], py[8], pz[8], dist[8];
#pragma unroll
    for (int i = 0; i < 8; ++i) {
        int n = tid + i*256;
        px[i] = sx[n]; py[i] = sy[n]; pz[i] = sz[n];
        dist[i] = 1e10f;
    }
    int far = 0, pb = 0;
    float* ob = out + b * 3 * SS;
    for (int it = 0; it < SS; ++it) {
        float cx = sx[far], cy = sy[far], cz = sz[far];
        if (tid == 0) { ob[it] = cx; ob[SS+it] = cy; ob[2*SS+it] = cz; }
        unsigned bb = 0u; unsigned bi = 0xffffffffu;
#pragma unroll
        for (int i = 0; i < 8; ++i) {
            float dx = px[i]-cx, dy = py[i]-cy, dz = pz[i]-cz;
            float d = dx*dx; d += dy*dy; d += dz*dz;
            float dd = fminf(dist[i], d); dist[i] = dd;
            unsigned bits = __float_as_uint(dd);   // monotone for dd >= 0
            if (bits > bb) { bb = bits; bi = (unsigned)(tid + i*256); }
        }
        unsigned wm = __reduce_max_sync(0xffffffffu, bb);
        unsigned cand = (bb == wm) ? bi : 0xffffffffu;
        unsigned wi = __reduce_min_sync(0xffffffffu, cand);   // first-index tie-break
        if (lane == 0) { swb[pb][wid] = wm; swi[pb][wid] = wi; }
        __syncthreads();
        unsigned b2 = swb[pb][lane & 7];
        unsigned i2 = swi[pb][lane & 7];
        unsigned m2 = __reduce_max_sync(0xffffffffu, b2);
        unsigned c2 = (b2 == m2) ? i2 : 0xffffffffu;
        far = (int)__reduce_min_sync(0xffffffffu, c2);
        pb ^= 1;
    }
}

// ---------------- ball query: smem-staged xyz; warp per center ----------------
__global__ __launch_bounds__(256)
void ball_kernel(const float* __restrict__ xyz,
                 const float* __restrict__ newxyz /* = d_out head */) {
    __shared__ float sx[NN], sy[NN], sz[NN];
    int b = blockIdx.x >> 6, schunk = blockIdx.x & 63;
    const float* xb = xyz + b * 3 * NN;
    for (int i = threadIdx.x; i < NN; i += 256) {
        sx[i] = xb[i]; sy[i] = xb[NN + i]; sz[i] = xb[2*NN + i];
    }
    __syncthreads();
    int w = threadIdx.x >> 5, lane = threadIdx.x & 31;
    int s = schunk * 8 + w;
    float cx = newxyz[b*3*SS + s];
    float cy = newxyz[b*3*SS + SS + s];
    float cz = newxyz[b*3*SS + 2*SS + s];
    int* dst = g_bidx + (b*SS + s) * KK;
    const float R2 = 0.04f;
    int count = 0, first = -1;
    for (int r = 0; r < NN/32; ++r) {
        int n = r*32 + lane;
        float dx = cx - sx[n], dy = cy - sy[n], dz = cz - sz[n];
        float d = dx*dx; d += dy*dy; d += dz*dz;
        bool q = (d <= R2);
        unsigned m = __ballot_sync(0xffffffffu, q);
        if (first < 0 && m) first = r*32 + __ffs(m) - 1;
        int pos = count + __popc(m & ((1u << lane) - 1u));
        if (q && pos < KK) dst[pos] = n;
        count += __popc(m);
        if (count >= KK) break;
    }
    if (count < KK && lane >= count && lane < KK) dst[lane] = first;
}

// ---------------- stats1: gather u1 + xyz-correction, BN1 stats ONLY (no y1 store) ----------------
__global__ __launch_bounds__(256)
void stats1_kernel(const float* __restrict__ w0, const float* __restrict__ newxyz) {
    __shared__ __align__(16) float Wc[3*64];       // Wc[c][o]
    __shared__ __align__(16) float red[2*16*64];   // stats overlay
    int tid = threadIdx.x;
    int og = tid & 15, o = og*4;
    int pgg = tid >> 4, pp = pgg*8;
    int pbase = blockIdx.x * 128;

    if (tid < 192) Wc[tid] = w0[(tid & 63)*C0 + (tid >> 6)];

    int gp0 = pbase + pp;
    int sg = gp0 >> 5;
    int b = sg >> 9, s = sg & 511;

    int4 ia = *(const int4*)(g_bidx + gp0);
    int4 ib = *(const int4*)(g_bidx + gp0 + 4);
    int nn[8] = {ia.x, ia.y, ia.z, ia.w, ib.x, ib.y, ib.z, ib.w};

    float4 u[8], xz[8];
#pragma unroll
    for (int i = 0; i < 8; ++i) {
        size_t base = ((size_t)(b*NN + nn[i])) * U1W;
        u[i]  = *(const float4*)(g_u1 + base + o);
        xz[i] = *(const float4*)(g_u1 + base + 64);
    }
    float cx = newxyz[b*3*SS + s];
    float cy = newxyz[b*3*SS + SS + s];
    float cz = newxyz[b*3*SS + 2*SS + s];
    __syncthreads();   // Wc ready

    float4 wc0 = *(const float4*)(Wc + o);
    float4 wc1 = *(const float4*)(Wc + 64 + o);
    float4 wc2 = *(const float4*)(Wc + 128 + o);
    ull_t wx[4] = {dup2(wc0.x), dup2(wc0.y), dup2(wc0.z), dup2(wc0.w)};
    ull_t wy[4] = {dup2(wc1.x), dup2(wc1.y), dup2(wc1.z), dup2(wc1.w)};
    ull_t wz[4] = {dup2(wc2.x), dup2(wc2.y), dup2(wc2.z), dup2(wc2.w)};

    float acc[8][4];
#pragma unroll
    for (int i2 = 0; i2 < 4; ++i2) {
        int p0 = 2*i2, p1 = 2*i2 + 1;
        ull_t dx2 = packf(xz[p0].x - cx, xz[p1].x - cx);
        ull_t dy2 = packf(xz[p0].y - cy, xz[p1].y - cy);
        ull_t dz2 = packf(xz[p0].z - cz, xz[p1].z - cz);
        float u0[4] = {u[p0].x, u[p0].y, u[p0].z, u[p0].w};
        float u1v[4] = {u[p1].x, u[p1].y, u[p1].z, u[p1].w};
#pragma unroll
        for (int j = 0; j < 4; ++j) {
            ull_t a = packf(u0[j], u1v[j]);
            FMA2(a, wx[j], dx2, a);
            FMA2(a, wy[j], dy2, a);
            FMA2(a, wz[j], dz2, a);
            acc[p0][j] = ull_lo(a);
            acc[p1][j] = ull_hi(a);
        }
    }

    float sj[4] = {0,0,0,0}, qj[4] = {0,0,0,0};
#pragma unroll
    for (int i = 0; i < 8; ++i)
#pragma unroll
        for (int j = 0; j < 4; ++j) { sj[j] += acc[i][j]; qj[j] += acc[i][j]*acc[i][j]; }
    {
        float4 a = {sj[0], sj[1], sj[2], sj[3]};
        float4 b2 = {qj[0], qj[1], qj[2], qj[3]};
        *(float4*)(red + pgg*64 + o) = a;
        *(float4*)(red + 1024 + pgg*64 + o) = b2;
    }
    __syncthreads();
    if (tid < 64) {
        float S = 0.f, Q = 0.f;
#pragma unroll
        for (int g = 0; g < 16; ++g) { S += red[g*64 + tid]; Q += red[1024 + g*64 + tid]; }
        atomicAdd(&g_stat1[tid], S);
        atomicAdd(&g_stat1[64 + tid], Q);
    }
}

// ---------------- conv2: recompute y1 from u1 (bit-exact), BN1+ReLU, GEMM(64->64) f32x2 ----------------
__global__ __launch_bounds__(256)
void conv2_kernel(const float* __restrict__ w1, const float* __restrict__ b1,
                  const float* __restrict__ g0, const float* __restrict__ bt0,
                  const float* __restrict__ w0, const float* __restrict__ newxyz) {
    extern __shared__ float sm[];
    float* Ws = sm;                 // [64][64]
    float* Xs = sm + 64*64;         // [64][128]
    float* sc1 = Xs + 64*128;       // [64]
    float* sh1 = sc1 + 64;          // [64]
    float* Wc = sh1 + 64;           // [3][64]
    int tid = threadIdx.x, lane = tid & 31, w = tid >> 5;
    int pbase = blockIdx.x * 128;

    // gather: 4 points (p0..p0+3), 8 channels (c0..c0+7) + xyz
    int p0 = lane*4;
    int gp0 = pbase + p0;
    int sg = gp0 >> 5;
    int b = sg >> 9, ss = sg & 511;
    int c0 = w*8;
    int4 ii = *(const int4*)(g_bidx + gp0);
    int nn[4] = {ii.x, ii.y, ii.z, ii.w};
    float4 ua[4], ub[4], xz[4];
#pragma unroll
    for (int i = 0; i < 4; ++i) {
        const float* base = g_u1 + ((size_t)(b*NN + nn[i]))*U1W;
        ua[i] = *(const float4*)(base + c0);
        ub[i] = *(const float4*)(base + c0 + 4);
        xz[i] = *(const float4*)(base + 64);
    }
    float cx = newxyz[b*3*SS + ss];
    float cy = newxyz[b*3*SS + SS + ss];
    float cz = newxyz[b*3*SS + 2*SS + ss];

    if (tid < 192) Wc[tid] = w0[(tid & 63)*C0 + (tid >> 6)];
    if (tid < 64) {
        float sc, sh;
        bn_coeff(g_stat1, O1, tid, g0, bt0, sc, sh);
        sc1[tid] = sc; sh1[tid] = sh;
    }
    {
        int o = tid & 63, cq = tid >> 6;
#pragma unroll
        for (int k = 0; k < 16; ++k) {
            int c = cq*16 + k;
            Ws[c*64 + o] = w1[o*64 + c];
        }
    }
    __syncthreads();

    // recompute y1 (identical FMA2 order to stats1 -> bit-exact), BN+ReLU, store Xs
    {
        float uu[4][8];
#pragma unroll
        for (int i = 0; i < 4; ++i) {
            uu[i][0]=ua[i].x; uu[i][1]=ua[i].y; uu[i][2]=ua[i].z; uu[i][3]=ua[i].w;
            uu[i][4]=ub[i].x; uu[i][5]=ub[i].y; uu[i][6]=ub[i].z; uu[i][7]=ub[i].w;
        }
        float4 wxa = *(const float4*)(Wc + c0),       wxb = *(const float4*)(Wc + c0 + 4);
        float4 wya = *(const float4*)(Wc + 64 + c0),  wyb = *(const float4*)(Wc + 64 + c0 + 4);
        float4 wza = *(const float4*)(Wc + 128 + c0), wzb = *(const float4*)(Wc + 128 + c0 + 4);
        float wxv[8] = {wxa.x,wxa.y,wxa.z,wxa.w, wxb.x,wxb.y,wxb.z,wxb.w};
        float wyv[8] = {wya.x,wya.y,wya.z,wya.w, wyb.x,wyb.y,wyb.z,wyb.w};
        float wzv[8] = {wza.x,wza.y,wza.z,wza.w, wzb.x,wzb.y,wzb.z,wzb.w};
        float y[4][8];
#pragma unroll
        for (int pr = 0; pr < 4; pr += 2) {
            ull_t dx2 = packf(xz[pr].x - cx, xz[pr+1].x - cx);
            ull_t dy2 = packf(xz[pr].y - cy, xz[pr+1].y - cy);
            ull_t dz2 = packf(xz[pr].z - cz, xz[pr+1].z - cz);
#pragma unroll
            for (int j = 0; j < 8; ++j) {
                ull_t a = packf(uu[pr][j], uu[pr+1][j]);
                FMA2(a, dup2(wxv[j]), dx2, a);
                FMA2(a, dup2(wyv[j]), dy2, a);
                FMA2(a, dup2(wzv[j]), dz2, a);
                y[pr][j] = ull_lo(a);
                y[pr+1][j] = ull_hi(a);
            }
        }
#pragma unroll
        for (int j = 0; j < 8; ++j) {
            float sc = sc1[c0+j], sh = sh1[c0+j];
            float4 v;
            v.x = fmaxf(fmaf(y[0][j], sc, sh), 0.f);
            v.y = fmaxf(fmaf(y[1][j], sc, sh), 0.f);
            v.z = fmaxf(fmaf(y[2][j], sc, sh), 0.f);
            v.w = fmaxf(fmaf(y[3][j], sc, sh), 0.f);
            *(float4*)(Xs + (c0+j)*128 + p0) = v;
        }
    }
    __syncthreads();

    int og = tid & 15, o = og*4;
    int pgg = tid >> 4, pp = pgg*8;
    ull_t accp[4][4];
#pragma unroll
    for (int i = 0; i < 4; ++i)
#pragma unroll
        for (int j = 0; j < 4; ++j) accp[i][j] = 0ull;
#pragma unroll 4
    for (int c = 0; c < 64; ++c) {
        ulonglong2 xa = *(const ulonglong2*)(Xs + c*128 + pp);
        ulonglong2 xb2 = *(const ulonglong2*)(Xs + c*128 + pp + 4);
        float4 wv = *(const float4*)(Ws + c*64 + o);
        ull_t xs[4] = {xa.x, xa.y, xb2.x, xb2.y};
        ull_t ws[4] = {dup2(wv.x), dup2(wv.y), dup2(wv.z), dup2(wv.w)};
#pragma unroll
        for (int i = 0; i < 4; ++i)
#pragma unroll
            for (int j = 0; j < 4; ++j)
                FMA2(accp[i][j], xs[i], ws[j], accp[i][j]);
    }
    float acc[8][4];
#pragma unroll
    for (int i = 0; i < 4; ++i)
#pragma unroll
        for (int j = 0; j < 4; ++j) {
            acc[2*i][j] = ull_lo(accp[i][j]);
            acc[2*i+1][j] = ull_hi(accp[i][j]);
        }
    float4 bias = *(const float4*)(b1 + o);
    float bv[4] = {bias.x, bias.y, bias.z, bias.w};
#pragma unroll
    for (int i = 0; i < 8; ++i)
#pragma unroll
        for (int j = 0; j < 4; ++j) acc[i][j] += bv[j];
#pragma unroll
    for (int j = 0; j < 4; ++j) {
        float* dst = g_bufB + (size_t)(o+j)*PP + pbase + pp;
        float4 u0 = {acc[0][j], acc[1][j], acc[2][j], acc[3][j]};
        float4 u1v = {acc[4][j], acc[5][j], acc[6][j], acc[7][j]};
        ((float4*)dst)[0] = u0; ((float4*)dst)[1] = u1v;
    }
    float sj[4] = {0,0,0,0}, qj[4] = {0,0,0,0};
#pragma unroll
    for (int i = 0; i < 8; ++i)
#pragma unroll
        for (int j = 0; j < 4; ++j) { sj[j] += acc[i][j]; qj[j] += acc[i][j]*acc[i][j]; }
    __syncthreads();
    float* red = Xs;
    {
        float4 a = {sj[0], sj[1], sj[2], sj[3]};
        float4 b2 = {qj[0], qj[1], qj[2], qj[3]};
        *(float4*)(red + pgg*64 + o) = a;
        *(float4*)(red + 1024 + pgg*64 + o) = b2;
    }
    __syncthreads();
    if (tid < 64) {
        float S = 0.f, Q = 0.f;
#pragma unroll
        for (int g = 0; g < 16; ++g) { S += red[g*64 + tid]; Q += red[1024 + g*64 + tid]; }
        atomicAdd(&g_stat2[tid], S);
        atomicAdd(&g_stat2[64 + tid], Q);
    }
}

// ---------------- conv3: BN2 coeff in-block, batched X loads, GEMM(64->128) f32x2, fused max/min ----------------
__global__ __launch_bounds__(256)
void conv3_kernel(const float* __restrict__ w2, const float* __restrict__ b2p,
                  const float* __restrict__ g1, const float* __restrict__ bt1) {
    extern __shared__ float sm[];
    float* Ws = sm;                 // [64][128]
    float* Xs = sm + 64*128;        // [64][128]
    float* sc2 = Xs + 64*128;       // [64]
    float* sh2 = sc2 + 64;          // [64]
    int tid = threadIdx.x, lane = tid & 31, w = tid >> 5;
    int pbase = blockIdx.x * 128;

    float4 v[8];
#pragma unroll
    for (int i = 0; i < 8; ++i)
        v[i] = *(const float4*)(g_bufB + (size_t)(w + i*8)*PP + pbase + lane*4);

    if (tid < 64) {
        float sc, sh;
        bn_coeff(g_stat2, O2, tid, g1, bt1, sc, sh);
        sc2[tid] = sc; sh2[tid] = sh;
    }
    {
        int o = tid & 127, ch = tid >> 7;
#pragma unroll
        for (int cc = 0; cc < 32; ++cc) {
            int c = ch*32 + cc;
            Ws[c*128 + o] = w2[o*64 + c];
        }
    }
    __syncthreads();
#pragma unroll
    for (int i = 0; i < 8; ++i) {
        int c = w + i*8;
        float sc = sc2[c], sh = sh2[c];
        float4 u = v[i];
        u.x = fmaxf(fmaf(u.x, sc, sh), 0.f);
        u.y = fmaxf(fmaf(u.y, sc, sh), 0.f);
        u.z = fmaxf(fmaf(u.z, sc, sh), 0.f);
        u.w = fmaxf(fmaf(u.w, sc, sh), 0.f);
        *(float4*)(Xs + c*128 + lane*4) = u;
    }
    __syncthreads();

    int og = tid & 15, o = og*8;
    int pgg = tid >> 4, pp = pgg*8;
    ull_t accp[4][8];
#pragma unroll
    for (int i = 0; i < 4; ++i)
#pragma unroll
        for (int j = 0; j < 8; ++j) accp[i][j] = 0ull;
#pragma unroll 2
    for (int c = 0; c < 64; ++c) {
        ulonglong2 xa = *(const ulonglong2*)(Xs + c*128 + pp);
        ulonglong2 xb2 = *(const ulonglong2*)(Xs + c*128 + pp + 4);
        float4 wa = *(const float4*)(Ws + c*128 + o);
        float4 wb = *(const float4*)(Ws + c*128 + o + 4);
        ull_t xs[4] = {xa.x, xa.y, xb2.x, xb2.y};
        ull_t ws[8] = {dup2(wa.x), dup2(wa.y), dup2(wa.z), dup2(wa.w),
                       dup2(wb.x), dup2(wb.y), dup2(wb.z), dup2(wb.w)};
#pragma unroll
        for (int i = 0; i < 4; ++i)
#pragma unroll
            for (int j = 0; j < 8; ++j)
                FMA2(accp[i][j], xs[i], ws[j], accp[i][j]);
    }
    float acc[8][8];
#pragma unroll
    for (int i = 0; i < 4; ++i)
#pragma unroll
        for (int j = 0; j < 8; ++j) {
            acc[2*i][j] = ull_lo(accp[i][j]);
            acc[2*i+1][j] = ull_hi(accp[i][j]);
        }
    float4 ba = *(const float4*)(b2p + o);
    float4 bbv = *(const float4*)(b2p + o + 4);
    float bv[8] = {ba.x, ba.y, ba.z, ba.w, bbv.x, bbv.y, bbv.z, bbv.w};
#pragma unroll
    for (int i = 0; i < 8; ++i)
#pragma unroll
        for (int j = 0; j < 8; ++j) acc[i][j] += bv[j];

    float sj[8], qj[8], mxv[8], mnv[8];
#pragma unroll
    for (int j = 0; j < 8; ++j) {
        sj[j] = acc[0][j]; qj[j] = acc[0][j]*acc[0][j];
        mxv[j] = acc[0][j]; mnv[j] = acc[0][j];
    }
#pragma unroll
    for (int i = 1; i < 8; ++i)
#pragma unroll
        for (int j = 0; j < 8; ++j) {
            sj[j] += acc[i][j]; qj[j] += acc[i][j]*acc[i][j];
            mxv[j] = fmaxf(mxv[j], acc[i][j]);
            mnv[j] = fminf(mnv[j], acc[i][j]);
        }
    __syncthreads();
    float* red = Xs;   // overlay: [4][16][128]
    {
        float4 a0 = {sj[0], sj[1], sj[2], sj[3]};
        float4 a1 = {sj[4], sj[5], sj[6], sj[7]};
        float4 q0 = {qj[0], qj[1], qj[2], qj[3]};
        float4 q1 = {qj[4], qj[5], qj[6], qj[7]};
        float4 m0 = {mxv[0], mxv[1], mxv[2], mxv[3]};
        float4 m1 = {mxv[4], mxv[5], mxv[6], mxv[7]};
        float4 n0 = {mnv[0], mnv[1], mnv[2], mnv[3]};
        float4 n1 = {mnv[4], mnv[5], mnv[6], mnv[7]};
        *(float4*)(red + pgg*128 + o) = a0;
        *(float4*)(red + pgg*128 + o + 4) = a1;
        *(float4*)(red + 2048 + pgg*128 + o) = q0;
        *(float4*)(red + 2048 + pgg*128 + o + 4) = q1;
        *(float4*)(red + 4096 + pgg*128 + o) = m0;
        *(float4*)(red + 4096 + pgg*128 + o + 4) = m1;
        *(float4*)(red + 6144 + pgg*128 + o) = n0;
        *(float4*)(red + 6144 + pgg*128 + o + 4) = n1;
    }
    __syncthreads();
    if (tid < 128) {
        float S = 0.f, Q = 0.f;
#pragma unroll
        for (int g = 0; g < 16; ++g) { S += red[g*128 + tid]; Q += red[2048 + g*128 + tid]; }
        atomicAdd(&g_stat3[tid], S);
        atomicAdd(&g_stat3[128 + tid], Q);
    }
#pragma unroll
    for (int t = tid; t < 512; t += 256) {
        int g4 = t >> 7, o2 = t & 127;
        float m = red[4096 + (g4*4)*128 + o2];
        float n2 = red[6144 + (g4*4)*128 + o2];
#pragma unroll
        for (int k = 1; k < 4; ++k) {
            m = fmaxf(m, red[4096 + (g4*4+k)*128 + o2]);
            n2 = fminf(n2, red[6144 + (g4*4+k)*128 + o2]);
        }
        g_max3[(size_t)o2*BSS + blockIdx.x*4 + g4] = m;
        g_min3[(size_t)o2*BSS + blockIdx.x*4 + g4] = n2;
    }
}

// ---------------- final: BN3 coeff per-thread + affine on max/min + ReLU ----------------
__global__ void final_kernel(float* __restrict__ out,
                             const float* __restrict__ g2,
                             const float* __restrict__ bt2) {
    int idx = blockIdx.x * 256 + threadIdx.x;
    int b = idx >> 16;
    int rem = idx & 65535;
    int o = rem >> 9;
    int s = rem & 511;
    float sc, sh;
    bn_coeff(g_stat3, O3, o, g2, bt2, sc, sh);
    float mx = g_max3[(size_t)o*BSS + b*512 + s];
    float mn = g_min3[(size_t)o*BSS + b*512 + s];
    float y = (sc >= 0.f) ? fmaf(sc, mx, sh) : fmaf(sc, mn, sh);
    out[BB*3*SS + idx] = fmaxf(y, 0.f);
}

// ---------------- launch ----------------
extern "C" void kernel_launch(void* const* d_in, const int* in_sizes, int n_in,
                              void* d_out, int out_size) {
    (void)in_sizes; (void)n_in; (void)out_size;
    const float* xyz = (const float*)d_in[0];
    const float* pts = (const float*)d_in[1];
    const float* w0  = (const float*)d_in[2];
    const float* b0  = (const float*)d_in[3];
    const float* g0  = (const float*)d_in[4];
    const float* bt0 = (const float*)d_in[5];
    const float* w1  = (const float*)d_in[6];
    const float* b1  = (const float*)d_in[7];
    const float* g1  = (const float*)d_in[8];
    const float* bt1 = (const float*)d_in[9];
    const float* w2  = (const float*)d_in[10];
    const float* b2  = (const float*)d_in[11];
    const float* g2  = (const float*)d_in[12];
    const float* bt2 = (const float*)d_in[13];
    float* out = (float*)d_out;

    const int smemU = (64*64 + 64*128)*4;
    const int smem2 = (64*64 + 64*128 + 128 + 192)*4;
    const int smem3 = (64*128 + 64*128 + 128)*4;
    cudaFuncSetAttribute(u1_kernel,  cudaFuncAttributeMaxDynamicSharedMemorySize, smemU);
    cudaFuncSetAttribute(conv2_kernel, cudaFuncAttributeMaxDynamicSharedMemorySize, smem2);
    cudaFuncSetAttribute(conv3_kernel, cudaFuncAttributeMaxDynamicSharedMemorySize, smem3);

    u1_kernel<<<BB*16, 256, smemU>>>(pts, w0, b0, xyz);
    fps_kernel<<<BB, 256>>>(xyz, out);
    ball_kernel<<<BB*64, 256>>>(xyz, out);
    stats1_kernel<<<PP/128, 256>>>(w0, out);
    conv2_kernel<<<PP/128, 256, smem2>>>(w1, b1, g0, bt0, w0, out);
    conv3_kernel<<<PP/128, 256, smem3>>>(w2, b2, g1, bt1);
    final_kernel<<<BB*O3*SS/256, 256>>>(out, g2, bt2);
}